// round 1
// baseline (speedup 1.0000x reference)
#include <cuda_runtime.h>
#include <math.h>
#include <stdint.h>

// ---------------- problem constants ----------------
#define BB 4
#define TT 2048
#define DD 1024
#define HH 16
#define DKV 64          // DK == DV == 64
#define RR 64
#define KSZ 4
#define BH (BB*HH)      // 64
#define MTOK (BB*TT)    // 8192
#define EPSF 1e-6f

// ---------------- scratch (no cudaMalloc allowed) ----------------
__device__ float g_qx[MTOK*DD];
__device__ float g_kx[MTOK*DD];
__device__ float g_vx[MTOK*DD];
__device__ float g_Q [MTOK*DD];
__device__ float g_K [MTOK*DD];
__device__ float g_V [MTOK*DD];
__device__ float g_alpha[MTOK*DD];
__device__ float g_O [MTOK*DD];
__device__ float g_hidA[MTOK*RR];
__device__ float g_hidG[MTOK*RR];
__device__ float g_beta[MTOK*HH];
__device__ float g_gate[MTOK*HH];

__device__ __forceinline__ float sigmoidf_(float v){ return 1.0f/(1.0f+expf(-v)); }
__device__ __forceinline__ float siluf_(float v){ return v/(1.0f+expf(-v)); }

// ---------------- fused causal depthwise conv (KS=4) + SiLU, 3 streams ----------------
__global__ void conv_silu_kernel(const float* __restrict__ x,
                                 const float* __restrict__ wq, const float* __restrict__ bq,
                                 const float* __restrict__ wk, const float* __restrict__ bk,
                                 const float* __restrict__ wv, const float* __restrict__ bv)
{
    int idx = blockIdx.x*blockDim.x + threadIdx.x;
    if (idx >= MTOK*DD) return;
    int d = idx % DD;
    int t = (idx / DD) % TT;
    int b = idx / (DD*TT);

    float xs[KSZ];
#pragma unroll
    for (int j = 0; j < KSZ; j++) {
        int tt = t - (KSZ-1) + j;
        xs[j] = (tt >= 0) ? x[((size_t)b*TT + tt)*DD + d] : 0.0f;
    }
    float aq = bq[d], ak = bk[d], av = bv[d];
#pragma unroll
    for (int j = 0; j < KSZ; j++) {
        aq = fmaf(xs[j], wq[d*KSZ + j], aq);
        ak = fmaf(xs[j], wk[d*KSZ + j], ak);
        av = fmaf(xs[j], wv[d*KSZ + j], av);
    }
    g_qx[idx] = siluf_(aq);
    g_kx[idx] = siluf_(ak);
    g_vx[idx] = siluf_(av);
}

// ---------------- big SGEMM: C[M,N] = A[M,K] @ W[K,N] + bias, optional activation ----
// BM=BN=128, BK=8, 256 threads, 8x8 per thread. Requires M%128==0, N%128==0, K%8==0.
template<int ACT>
__global__ __launch_bounds__(256)
void gemm128(const float* __restrict__ A, const float* __restrict__ W,
             const float* __restrict__ bias, float* __restrict__ C,
             int M, int N, int K)
{
    __shared__ float As[8][128];
    __shared__ float Bs[8][128];

    const int tid = threadIdx.x;
    const int m0 = blockIdx.y * 128;
    const int n0 = blockIdx.x * 128;
    const int ty = tid >> 4;        // 0..15
    const int tx = tid & 15;        // 0..15

    const int arow = tid >> 1;          // 0..127
    const int ak   = (tid & 1) * 4;     // 0 or 4
    const int brow = tid >> 5;          // 0..7
    const int bcol = (tid & 31) * 4;    // 0..124

    float acc[8][8];
#pragma unroll
    for (int i = 0; i < 8; i++)
#pragma unroll
        for (int j = 0; j < 8; j++) acc[i][j] = 0.0f;

    for (int k0 = 0; k0 < K; k0 += 8) {
        float4 a4 = *reinterpret_cast<const float4*>(&A[(size_t)(m0 + arow)*K + k0 + ak]);
        float4 b4 = *reinterpret_cast<const float4*>(&W[(size_t)(k0 + brow)*N + n0 + bcol]);
        __syncthreads();
        As[ak+0][arow] = a4.x; As[ak+1][arow] = a4.y;
        As[ak+2][arow] = a4.z; As[ak+3][arow] = a4.w;
        *reinterpret_cast<float4*>(&Bs[brow][bcol]) = b4;
        __syncthreads();
#pragma unroll
        for (int k = 0; k < 8; k++) {
            float ra[8], rb[8];
#pragma unroll
            for (int i = 0; i < 8; i++) ra[i] = As[k][ty*8 + i];
#pragma unroll
            for (int i = 0; i < 8; i++) rb[i] = Bs[k][tx*8 + i];
#pragma unroll
            for (int i = 0; i < 8; i++)
#pragma unroll
                for (int j = 0; j < 8; j++)
                    acc[i][j] = fmaf(ra[i], rb[j], acc[i][j]);
        }
    }

#pragma unroll
    for (int i = 0; i < 8; i++) {
        int m = m0 + ty*8 + i;
#pragma unroll
        for (int j = 0; j < 8; j++) {
            int n = n0 + tx*8 + j;
            float c = acc[i][j] + bias[n];
            if (ACT == 1) c = siluf_(c);
            else if (ACT == 2) c = sigmoidf_(c);
            C[(size_t)m*N + n] = c;
        }
    }
}

// ---------------- small/generic SGEMM: BM=BN=64, BK=16, 4x4 per thread --------------
template<int ACT>
__global__ __launch_bounds__(256)
void gemm_small(const float* __restrict__ A, const float* __restrict__ W,
                const float* __restrict__ bias, float* __restrict__ C,
                int M, int N, int K)
{
    __shared__ float As[16][64];
    __shared__ float Bs[16][64];

    const int tid = threadIdx.x;
    const int m0 = blockIdx.y * 64;
    const int n0 = blockIdx.x * 64;
    const int ty = tid >> 4, tx = tid & 15;

    float acc[4][4];
#pragma unroll
    for (int i = 0; i < 4; i++)
#pragma unroll
        for (int j = 0; j < 4; j++) acc[i][j] = 0.0f;

    const int r  = tid >> 2,  c  = (tid & 3)  * 4;   // A tile: 64 rows x 16 k
    const int r2 = tid >> 4,  c2 = (tid & 15) * 4;   // B tile: 16 k  x 64 n

    for (int k0 = 0; k0 < K; k0 += 16) {
        __syncthreads();
#pragma unroll
        for (int i = 0; i < 4; i++) {
            int kk = k0 + c + i;
            int mm = m0 + r;
            As[c+i][r] = (kk < K && mm < M) ? A[(size_t)mm*K + kk] : 0.0f;
        }
#pragma unroll
        for (int i = 0; i < 4; i++) {
            int nn = n0 + c2 + i;
            int kk = k0 + r2;
            Bs[r2][c2+i] = (kk < K && nn < N) ? W[(size_t)kk*N + nn] : 0.0f;
        }
        __syncthreads();
#pragma unroll
        for (int k = 0; k < 16; k++) {
            float ra[4], rb[4];
#pragma unroll
            for (int i = 0; i < 4; i++) ra[i] = As[k][ty*4 + i];
#pragma unroll
            for (int i = 0; i < 4; i++) rb[i] = Bs[k][tx*4 + i];
#pragma unroll
            for (int i = 0; i < 4; i++)
#pragma unroll
                for (int j = 0; j < 4; j++)
                    acc[i][j] = fmaf(ra[i], rb[j], acc[i][j]);
        }
    }

#pragma unroll
    for (int i = 0; i < 4; i++) {
        int m = m0 + ty*4 + i;
        if (m >= M) continue;
#pragma unroll
        for (int j = 0; j < 4; j++) {
            int n = n0 + tx*4 + j;
            if (n >= N) continue;
            float cv = acc[i][j] + bias[n];
            if (ACT == 1) cv = siluf_(cv);
            else if (ACT == 2) cv = sigmoidf_(cv);
            C[(size_t)m*N + n] = cv;
        }
    }
}

// ---------------- L2 normalize each contiguous group of 64 (one warp/group) ---------
__global__ void l2norm_kernel(float* __restrict__ Z, int ngroups)
{
    int warp = (blockIdx.x*blockDim.x + threadIdx.x) >> 5;
    int lane = threadIdx.x & 31;
    if (warp >= ngroups) return;
    float* p = Z + (size_t)warp * 64;
    float a = p[lane];
    float b = p[lane + 32];
    float ss = a*a + b*b;
#pragma unroll
    for (int o = 16; o; o >>= 1) ss += __shfl_xor_sync(0xFFFFFFFFu, ss, o);
    float rn = rsqrtf(fmaxf(ss, EPSF));
    p[lane]      = a * rn;
    p[lane + 32] = b * rn;
}

// ---------------- sequential gated delta-rule scan --------------------------------
// one block per head (BH=64), 64 threads; thread j owns state column S[:, j]
__global__ __launch_bounds__(64)
void scan_kernel(const float* __restrict__ Q, const float* __restrict__ K,
                 const float* __restrict__ V, const float* __restrict__ A,
                 const float* __restrict__ Beta,
                 float* __restrict__ O, float* __restrict__ Sout)
{
    const int bh = blockIdx.x;
    const int b = bh / HH, h = bh % HH;
    const int j = threadIdx.x;

    __shared__ float sq[2][64], sk[2][64], sa[2][64];

    float S[64];
#pragma unroll
    for (int i = 0; i < 64; i++) S[i] = 0.0f;

    const size_t base0 = ((size_t)b*TT)*DD + h*64;

    // preload t=0
    sq[0][j] = Q[base0 + j];
    sk[0][j] = K[base0 + j];
    sa[0][j] = A[base0 + j];
    float vj  = V[base0 + j];
    float bta = Beta[((size_t)b*TT)*HH + h];
    __syncthreads();

    for (int t = 0; t < TT; t++) {
        const int cur = t & 1;
        float vn = 0.0f, btan = 0.0f;
        if (t + 1 < TT) {
            size_t bs = base0 + (size_t)(t+1)*DD;
            sq[cur^1][j] = Q[bs + j];
            sk[cur^1][j] = K[bs + j];
            sa[cur^1][j] = A[bs + j];
            vn   = V[bs + j];
            btan = Beta[((size_t)b*TT + (t+1))*HH + h];
        }

        // decay + kTS (4 partial accumulators to break RAW chains)
        float k0 = 0.f, k1 = 0.f, k2 = 0.f, k3 = 0.f;
#pragma unroll
        for (int i = 0; i < 64; i += 4) {
            S[i+0] *= sa[cur][i+0]; k0 = fmaf(sk[cur][i+0], S[i+0], k0);
            S[i+1] *= sa[cur][i+1]; k1 = fmaf(sk[cur][i+1], S[i+1], k1);
            S[i+2] *= sa[cur][i+2]; k2 = fmaf(sk[cur][i+2], S[i+2], k2);
            S[i+3] *= sa[cur][i+3]; k3 = fmaf(sk[cur][i+3], S[i+3], k3);
        }
        float kts = (k0 + k1) + (k2 + k3);
        float dlt = bta * (vj - kts);

        float o0 = 0.f, o1 = 0.f, o2 = 0.f, o3 = 0.f;
#pragma unroll
        for (int i = 0; i < 64; i += 4) {
            S[i+0] = fmaf(sk[cur][i+0], dlt, S[i+0]); o0 = fmaf(S[i+0], sq[cur][i+0], o0);
            S[i+1] = fmaf(sk[cur][i+1], dlt, S[i+1]); o1 = fmaf(S[i+1], sq[cur][i+1], o1);
            S[i+2] = fmaf(sk[cur][i+2], dlt, S[i+2]); o2 = fmaf(S[i+2], sq[cur][i+2], o2);
            S[i+3] = fmaf(sk[cur][i+3], dlt, S[i+3]); o3 = fmaf(S[i+3], sq[cur][i+3], o3);
        }
        float o = (o0 + o1) + (o2 + o3);

        O[(((size_t)b*TT + t)*HH + h)*64 + j] = o;

        vj = vn; bta = btan;
        __syncthreads();
    }

#pragma unroll
    for (int i = 0; i < 64; i++)
        Sout[(size_t)bh*DKV*DKV + (size_t)i*DKV + j] = S[i];
}

// ---------------- headwise RMSNorm + output gate (in place on O) -------------------
__global__ __launch_bounds__(256)
void normgate_kernel(float* __restrict__ O, const float* __restrict__ rms_w,
                     const float* __restrict__ gate)
{
    // 4 rows (of 64) per 256-thread block; row index over MTOK*HH
    int row = blockIdx.x*4 + (threadIdx.x >> 6);
    int j   = threadIdx.x & 63;
    int h   = row % HH;

    float v = O[(size_t)row*64 + j];
    float ss = v*v;
#pragma unroll
    for (int o = 16; o; o >>= 1) ss += __shfl_xor_sync(0xFFFFFFFFu, ss, o);

    __shared__ float part[8];
    if ((threadIdx.x & 31) == 0) part[threadIdx.x >> 5] = ss;
    __syncthreads();
    int w0 = (threadIdx.x >> 6) * 2;
    float tot = part[w0] + part[w0 + 1];

    float rn = rsqrtf(tot * (1.0f/64.0f) + EPSF);
    float g  = gate[row];
    O[(size_t)row*64 + j] = v * rn * rms_w[h*64 + j] * g;
}

// ---------------- launch -----------------------------------------------------------
extern "C" void kernel_launch(void* const* d_in, const int* in_sizes, int n_in,
                              void* d_out, int out_size)
{
    const float* x       = (const float*)d_in[0];
    const float* conv_qw = (const float*)d_in[1];
    const float* conv_qb = (const float*)d_in[2];
    const float* conv_kw = (const float*)d_in[3];
    const float* conv_kb = (const float*)d_in[4];
    const float* conv_vw = (const float*)d_in[5];
    const float* conv_vb = (const float*)d_in[6];
    const float* Wq      = (const float*)d_in[7];
    const float* bq      = (const float*)d_in[8];
    const float* Wk      = (const float*)d_in[9];
    const float* bk      = (const float*)d_in[10];
    const float* Wv      = (const float*)d_in[11];
    const float* bv      = (const float*)d_in[12];
    const float* W_ad    = (const float*)d_in[13];
    const float* b_ad    = (const float*)d_in[14];
    const float* W_au    = (const float*)d_in[15];
    const float* b_au    = (const float*)d_in[16];
    const float* W_beta  = (const float*)d_in[17];
    const float* b_beta  = (const float*)d_in[18];
    const float* rms_w   = (const float*)d_in[19];
    const float* W_gd    = (const float*)d_in[20];
    const float* b_gd    = (const float*)d_in[21];
    const float* W_gu    = (const float*)d_in[22];
    const float* b_gu    = (const float*)d_in[23];
    const float* Wo      = (const float*)d_in[24];
    const float* bo      = (const float*)d_in[25];

    float* out = (float*)d_out;
    float* y = out;                                   // [B,T,D]
    const size_t y_elems = (size_t)MTOK * DD;
    const size_t s_elems = (size_t)BH * DKV * DKV;
    // S_final defensively placed at the tail of the output buffer
    float* Sout = out + ((size_t)out_size >= y_elems + s_elems
                         ? (size_t)out_size - s_elems : y_elems);

    float *qx, *kx, *vx, *Qp, *Kp, *Vp, *Al, *Op, *hA, *hG, *Bt, *Gt;
    cudaGetSymbolAddress((void**)&qx, g_qx);
    cudaGetSymbolAddress((void**)&kx, g_kx);
    cudaGetSymbolAddress((void**)&vx, g_vx);
    cudaGetSymbolAddress((void**)&Qp, g_Q);
    cudaGetSymbolAddress((void**)&Kp, g_K);
    cudaGetSymbolAddress((void**)&Vp, g_V);
    cudaGetSymbolAddress((void**)&Al, g_alpha);
    cudaGetSymbolAddress((void**)&Op, g_O);
    cudaGetSymbolAddress((void**)&hA, g_hidA);
    cudaGetSymbolAddress((void**)&hG, g_hidG);
    cudaGetSymbolAddress((void**)&Bt, g_beta);
    cudaGetSymbolAddress((void**)&Gt, g_gate);

    // 1) causal depthwise convs + SiLU
    conv_silu_kernel<<<(MTOK*DD + 255)/256, 256>>>(x, conv_qw, conv_qb,
                                                   conv_kw, conv_kb, conv_vw, conv_vb);

    // 2) Q/K/V projections (full SGEMM)
    dim3 gBig(DD/128, MTOK/128);
    gemm128<0><<<gBig, 256>>>(qx, Wq, bq, Qp, MTOK, DD, DD);
    gemm128<0><<<gBig, 256>>>(kx, Wk, bk, Kp, MTOK, DD, DD);
    gemm128<0><<<gBig, 256>>>(vx, Wv, bv, Vp, MTOK, DD, DD);

    // 3) L2 norm per (token, head) 64-group for Q and K
    int ngroups = MTOK * HH;
    int l2blocks = (ngroups*32 + 255)/256;
    l2norm_kernel<<<l2blocks, 256>>>(Qp, ngroups);
    l2norm_kernel<<<l2blocks, 256>>>(Kp, ngroups);

    // 4) alpha = sigmoid(silu(x@W_ad+b_ad) @ W_au + b_au)
    gemm_small<1><<<dim3(1, MTOK/64), 256>>>(x, W_ad, b_ad, hA, MTOK, RR, DD);
    gemm128<2><<<gBig, 256>>>(hA, W_au, b_au, Al, MTOK, DD, RR);

    // 5) beta = sigmoid(x@W_beta + b_beta)
    gemm_small<2><<<dim3(1, MTOK/64), 256>>>(x, W_beta, b_beta, Bt, MTOK, HH, DD);

    // 6) gate = sigmoid(silu(x@W_gd+b_gd) @ W_gu + b_gu)
    gemm_small<1><<<dim3(1, MTOK/64), 256>>>(x, W_gd, b_gd, hG, MTOK, RR, DD);
    gemm_small<2><<<dim3(1, MTOK/64), 256>>>(hG, W_gu, b_gu, Gt, MTOK, HH, RR);

    // 7) sequential delta-rule scan (also emits S_final)
    scan_kernel<<<BH, 64>>>(Qp, Kp, Vp, Al, Bt, Op, Sout);

    // 8) RMSNorm + gate (in place)
    normgate_kernel<<<(MTOK*HH)/4, 256>>>(Op, rms_w, Gt);

    // 9) y = O @ Wo + bo
    gemm128<0><<<gBig, 256>>>(Op, Wo, bo, y, MTOK, DD, DD);
}

// round 3
// speedup vs baseline: 1.2331x; 1.2331x over previous
#include <cuda_runtime.h>
#include <cuda_bf16.h>
#include <math.h>
#include <stdint.h>

// ---------------- problem constants ----------------
#define BB 4
#define TT 2048
#define DD 1024
#define HH 16
#define DKV 64
#define RR 64
#define KSZ 4
#define BH (BB*HH)      // 64
#define MTOK (BB*TT)    // 8192
#define EPSF 1e-6f

// ---------------- scratch (no cudaMalloc allowed) ----------------
__device__ __nv_bfloat16 g_qxh[MTOK*DD], g_qxl[MTOK*DD];
__device__ __nv_bfloat16 g_kxh[MTOK*DD], g_kxl[MTOK*DD];
__device__ __nv_bfloat16 g_vxh[MTOK*DD], g_vxl[MTOK*DD];
__device__ __nv_bfloat16 g_oh [MTOK*DD], g_ol [MTOK*DD];
__device__ __nv_bfloat16 g_wqh[DD*DD], g_wql[DD*DD];
__device__ __nv_bfloat16 g_wkh[DD*DD], g_wkl[DD*DD];
__device__ __nv_bfloat16 g_wvh[DD*DD], g_wvl[DD*DD];
__device__ __nv_bfloat16 g_woh[DD*DD], g_wol[DD*DD];
__device__ float g_Q [MTOK*DD];
__device__ float g_K [MTOK*DD];
__device__ float g_V [MTOK*DD];
__device__ float g_alpha[MTOK*DD];
__device__ float g_O [MTOK*DD];
__device__ float g_hidA[MTOK*RR];
__device__ float g_hidG[MTOK*RR];
__device__ float g_beta[MTOK*HH];
__device__ float g_gate[MTOK*HH];

__device__ __forceinline__ float sigmoidf_(float v){ return 1.0f/(1.0f+expf(-v)); }
__device__ __forceinline__ float siluf_(float v){ return v/(1.0f+expf(-v)); }

// ---------------- PTX helpers (baseline ISA only; NO sm_100a features) -------------
__device__ __forceinline__ uint32_t smem_u32(const void* p){
    uint32_t a;
    asm("{ .reg .u64 t; cvta.to.shared.u64 t, %1; cvt.u32.u64 %0, t; }" : "=r"(a) : "l"(p));
    return a;
}
#define CP_COMMIT() asm volatile("cp.async.commit_group;" ::: "memory")
#define CP_WAIT2()  asm volatile("cp.async.wait_group 2;" ::: "memory")
__device__ __forceinline__ void cp16(uint32_t dst, const void* src){
    asm volatile("cp.async.cg.shared.global [%0], [%1], 16;" :: "r"(dst), "l"(src) : "memory");
}
__device__ __forceinline__ void ldm4(uint32_t* r, uint32_t addr){
    asm volatile("ldmatrix.sync.aligned.m8n8.x4.shared.b16 {%0,%1,%2,%3}, [%4];"
        : "=r"(r[0]), "=r"(r[1]), "=r"(r[2]), "=r"(r[3]) : "r"(addr));
}
__device__ __forceinline__ void mma16816(float* d, const uint32_t* a, const uint32_t* b){
    asm volatile("mma.sync.aligned.m16n8k16.row.col.f32.bf16.bf16.f32 "
        "{%0,%1,%2,%3}, {%4,%5,%6,%7}, {%8,%9}, {%0,%1,%2,%3};"
        : "+f"(d[0]), "+f"(d[1]), "+f"(d[2]), "+f"(d[3])
        : "r"(a[0]), "r"(a[1]), "r"(a[2]), "r"(a[3]), "r"(b[0]), "r"(b[1]));
}

// ---------------- conv + SiLU, emits bf16 hi/lo splits ----------------
__global__ void conv_silu_split(const float* __restrict__ x,
                                const float* __restrict__ wq, const float* __restrict__ bq,
                                const float* __restrict__ wk, const float* __restrict__ bk,
                                const float* __restrict__ wv, const float* __restrict__ bv)
{
    int idx = blockIdx.x*blockDim.x + threadIdx.x;
    if (idx >= MTOK*DD) return;
    int d = idx % DD;
    int t = (idx / DD) % TT;
    int b = idx / (DD*TT);

    float xs[KSZ];
#pragma unroll
    for (int j = 0; j < KSZ; j++) {
        int tt = t - (KSZ-1) + j;
        xs[j] = (tt >= 0) ? x[((size_t)b*TT + tt)*DD + d] : 0.0f;
    }
    float aq = bq[d], ak = bk[d], av = bv[d];
#pragma unroll
    for (int j = 0; j < KSZ; j++) {
        aq = fmaf(xs[j], wq[d*KSZ + j], aq);
        ak = fmaf(xs[j], wk[d*KSZ + j], ak);
        av = fmaf(xs[j], wv[d*KSZ + j], av);
    }
    float q = siluf_(aq), k = siluf_(ak), v = siluf_(av);
    __nv_bfloat16 h;
    h = __float2bfloat16(q); g_qxh[idx] = h; g_qxl[idx] = __float2bfloat16(q - __bfloat162float(h));
    h = __float2bfloat16(k); g_kxh[idx] = h; g_kxl[idx] = __float2bfloat16(k - __bfloat162float(h));
    h = __float2bfloat16(v); g_vxh[idx] = h; g_vxl[idx] = __float2bfloat16(v - __bfloat162float(h));
}

// ---------------- W [K,N] f32 -> Wt hi/lo [N,K] bf16 (transpose + split) -----------
__global__ void wsplit(const float* __restrict__ W,
                       __nv_bfloat16* __restrict__ Th, __nv_bfloat16* __restrict__ Tl)
{
    __shared__ float tile[32][33];
    int k = blockIdx.y*32 + threadIdx.y;
    int n = blockIdx.x*32 + threadIdx.x;
    tile[threadIdx.y][threadIdx.x] = W[(size_t)k*DD + n];
    __syncthreads();
    int n2 = blockIdx.x*32 + threadIdx.y;
    int k2 = blockIdx.y*32 + threadIdx.x;
    float v = tile[threadIdx.x][threadIdx.y];
    __nv_bfloat16 h = __float2bfloat16(v);
    Th[(size_t)n2*DD + k2] = h;
    Tl[(size_t)n2*DD + k2] = __float2bfloat16(v - __bfloat162float(h));
}

// ---------------- HMMA bf16-split GEMM ----------------------------------------------
// C[M,N] = (Ah+Al)[M,1024] @ (Bh+Bl)[N,1024]^T + bias  (3 passes: hh, hl, lh)
// BM=BN=128, BK=32, 256 threads (8 warps as 2m x 4n), 4-stage cp.async pipeline.
// Smem rows padded to 80B -> ldmatrix bank-conflict-free.
#define STAGES 4
#define AROWB 80
#define STAGE_A_BYTES (128*AROWB)           // 10240
#define STAGE_BYTES   (2*STAGE_A_BYTES)     // 20480
#define HG_SMEM       (STAGES*STAGE_BYTES)  // 81920
#define HG_NIT 96                            // 3 segments * 32 k-iters

__global__ __launch_bounds__(256)
void hgemm(const __nv_bfloat16* __restrict__ Ahp, const __nv_bfloat16* __restrict__ Alp,
           const __nv_bfloat16* __restrict__ Bhp, const __nv_bfloat16* __restrict__ Blp,
           const float* __restrict__ bias, float* __restrict__ C, int N_)
{
    extern __shared__ char smem[];
    uint32_t sb = smem_u32(smem);
    const int tid = threadIdx.x;
    const int wid = tid >> 5, lane = tid & 31;
    const int warp_m = wid >> 2, warp_n = wid & 3;
    const int m0 = blockIdx.y << 7, n0 = blockIdx.x << 7;

    float acc[4][4][4];
#pragma unroll
    for (int i = 0; i < 4; i++)
#pragma unroll
        for (int j = 0; j < 4; j++)
#pragma unroll
            for (int k = 0; k < 4; k++) acc[i][j][k] = 0.0f;

    const int lrow = tid >> 1;          // 0..127
    const int lcb  = (tid & 1) * 2;     // chunk base 0 or 2

    auto load_stage = [&](int it) {
        int seg = it >> 5;
        int kk  = (it & 31) << 5;       // k offset in elements
        const __nv_bfloat16* A = (seg == 2) ? Alp : Ahp;
        const __nv_bfloat16* B = (seg == 1) ? Blp : Bhp;
        uint32_t st = sb + (uint32_t)(it & (STAGES-1)) * STAGE_BYTES;
        const __nv_bfloat16* ga = A + (size_t)(m0 + lrow)*DD + kk + lcb*8;
        uint32_t da = st + lrow*AROWB + lcb*16;
        cp16(da,      ga);
        cp16(da + 16, ga + 8);
        const __nv_bfloat16* gb = B + (size_t)(n0 + lrow)*DD + kk + lcb*8;
        uint32_t db = st + STAGE_A_BYTES + lrow*AROWB + lcb*16;
        cp16(db,      gb);
        cp16(db + 16, gb + 8);
        CP_COMMIT();
    };

    load_stage(0); load_stage(1); load_stage(2);

    // lane-dependent ldmatrix address pieces
    const uint32_t a_row = warp_m*64 + (lane & 15);
    const uint32_t a_col = (lane >> 4) * 16;
    const uint32_t b_row = warp_n*32 + (lane & 7) + ((lane >> 4) & 1) * 8;
    const uint32_t b_col = ((lane >> 3) & 1) * 16;

    for (int i = 0; i < HG_NIT; i++) {
        CP_WAIT2();
        __syncthreads();
        int j = i + 3;
        if (j < HG_NIT) load_stage(j); else CP_COMMIT();

        uint32_t st = sb + (uint32_t)(i & (STAGES-1)) * STAGE_BYTES;
#pragma unroll
        for (int ks = 0; ks < 2; ks++) {
            uint32_t afr[4][4], bfr[2][4];
            uint32_t abase = st + a_row*AROWB + ks*32 + a_col;
#pragma unroll
            for (int mf = 0; mf < 4; mf++) ldm4(afr[mf], abase + mf*(16*AROWB));
            uint32_t bbase = st + STAGE_A_BYTES + b_row*AROWB + ks*32 + b_col;
#pragma unroll
            for (int np = 0; np < 2; np++) ldm4(bfr[np], bbase + np*(16*AROWB));
#pragma unroll
            for (int mf = 0; mf < 4; mf++)
#pragma unroll
                for (int nf = 0; nf < 4; nf++)
                    mma16816(acc[mf][nf], afr[mf], &bfr[nf >> 1][(nf & 1) * 2]);
        }
    }

    // epilogue
    const int trow = lane >> 2, tcol = (lane & 3) * 2;
#pragma unroll
    for (int mf = 0; mf < 4; mf++) {
        int r = m0 + warp_m*64 + mf*16 + trow;
#pragma unroll
        for (int nf = 0; nf < 4; nf++) {
            int c = n0 + warp_n*32 + nf*8 + tcol;
            float b0 = bias[c], b1 = bias[c+1];
            float* p0 = C + (size_t)r*N_ + c;
            float* p1 = C + (size_t)(r+8)*N_ + c;
            p0[0] = acc[mf][nf][0] + b0; p0[1] = acc[mf][nf][1] + b1;
            p1[0] = acc[mf][nf][2] + b0; p1[1] = acc[mf][nf][3] + b1;
        }
    }
}

// ---------------- fp32 SGEMM 128x128 (alpha-up, K=64) ------------------------------
template<int ACT>
__global__ __launch_bounds__(256)
void gemm128(const float* __restrict__ A, const float* __restrict__ W,
             const float* __restrict__ bias, float* __restrict__ C,
             int M, int N, int K)
{
    __shared__ float As[8][128];
    __shared__ float Bs[8][128];

    const int tid = threadIdx.x;
    const int m0 = blockIdx.y * 128;
    const int n0 = blockIdx.x * 128;
    const int ty = tid >> 4;
    const int tx = tid & 15;
    const int arow = tid >> 1;
    const int ak   = (tid & 1) * 4;
    const int brow = tid >> 5;
    const int bcol = (tid & 31) * 4;

    float acc[8][8];
#pragma unroll
    for (int i = 0; i < 8; i++)
#pragma unroll
        for (int j = 0; j < 8; j++) acc[i][j] = 0.0f;

    for (int k0 = 0; k0 < K; k0 += 8) {
        float4 a4 = *reinterpret_cast<const float4*>(&A[(size_t)(m0 + arow)*K + k0 + ak]);
        float4 b4 = *reinterpret_cast<const float4*>(&W[(size_t)(k0 + brow)*N + n0 + bcol]);
        __syncthreads();
        As[ak+0][arow] = a4.x; As[ak+1][arow] = a4.y;
        As[ak+2][arow] = a4.z; As[ak+3][arow] = a4.w;
        *reinterpret_cast<float4*>(&Bs[brow][bcol]) = b4;
        __syncthreads();
#pragma unroll
        for (int k = 0; k < 8; k++) {
            float ra[8], rb[8];
#pragma unroll
            for (int i = 0; i < 8; i++) ra[i] = As[k][ty*8 + i];
#pragma unroll
            for (int i = 0; i < 8; i++) rb[i] = Bs[k][tx*8 + i];
#pragma unroll
            for (int i = 0; i < 8; i++)
#pragma unroll
                for (int j = 0; j < 8; j++)
                    acc[i][j] = fmaf(ra[i], rb[j], acc[i][j]);
        }
    }

#pragma unroll
    for (int i = 0; i < 8; i++) {
        int m = m0 + ty*8 + i;
#pragma unroll
        for (int j = 0; j < 8; j++) {
            int n = n0 + tx*8 + j;
            float c = acc[i][j] + bias[n];
            if (ACT == 1) c = siluf_(c);
            else if (ACT == 2) c = sigmoidf_(c);
            C[(size_t)m*N + n] = c;
        }
    }
}

// ---------------- small SGEMM (beta/gate/alpha-down) --------------------------------
template<int ACT>
__global__ __launch_bounds__(256)
void gemm_small(const float* __restrict__ A, const float* __restrict__ W,
                const float* __restrict__ bias, float* __restrict__ C,
                int M, int N, int K)
{
    __shared__ float As[16][64];
    __shared__ float Bs[16][64];

    const int tid = threadIdx.x;
    const int m0 = blockIdx.y * 64;
    const int n0 = blockIdx.x * 64;
    const int ty = tid >> 4, tx = tid & 15;

    float acc[4][4];
#pragma unroll
    for (int i = 0; i < 4; i++)
#pragma unroll
        for (int j = 0; j < 4; j++) acc[i][j] = 0.0f;

    const int r  = tid >> 2,  c  = (tid & 3)  * 4;
    const int r2 = tid >> 4,  c2 = (tid & 15) * 4;

    for (int k0 = 0; k0 < K; k0 += 16) {
        __syncthreads();
#pragma unroll
        for (int i = 0; i < 4; i++) {
            int kk = k0 + c + i;
            int mm = m0 + r;
            As[c+i][r] = (kk < K && mm < M) ? A[(size_t)mm*K + kk] : 0.0f;
        }
#pragma unroll
        for (int i = 0; i < 4; i++) {
            int nn = n0 + c2 + i;
            int kk = k0 + r2;
            Bs[r2][c2+i] = (kk < K && nn < N) ? W[(size_t)kk*N + nn] : 0.0f;
        }
        __syncthreads();
#pragma unroll
        for (int k = 0; k < 16; k++) {
            float ra[4], rb[4];
#pragma unroll
            for (int i = 0; i < 4; i++) ra[i] = As[k][ty*4 + i];
#pragma unroll
            for (int i = 0; i < 4; i++) rb[i] = Bs[k][tx*4 + i];
#pragma unroll
            for (int i = 0; i < 4; i++)
#pragma unroll
                for (int j = 0; j < 4; j++)
                    acc[i][j] = fmaf(ra[i], rb[j], acc[i][j]);
        }
    }

#pragma unroll
    for (int i = 0; i < 4; i++) {
        int m = m0 + ty*4 + i;
        if (m >= M) continue;
#pragma unroll
        for (int j = 0; j < 4; j++) {
            int n = n0 + tx*4 + j;
            if (n >= N) continue;
            float cv = acc[i][j] + bias[n];
            if (ACT == 1) cv = siluf_(cv);
            else if (ACT == 2) cv = sigmoidf_(cv);
            C[(size_t)m*N + n] = cv;
        }
    }
}

// ---------------- L2 normalize each contiguous 64-group ----------------------------
__global__ void l2norm_kernel(float* __restrict__ Z, int ngroups)
{
    int warp = (blockIdx.x*blockDim.x + threadIdx.x) >> 5;
    int lane = threadIdx.x & 31;
    if (warp >= ngroups) return;
    float* p = Z + (size_t)warp * 64;
    float a = p[lane];
    float b = p[lane + 32];
    float ss = a*a + b*b;
#pragma unroll
    for (int o = 16; o; o >>= 1) ss += __shfl_xor_sync(0xFFFFFFFFu, ss, o);
    float rn = rsqrtf(fmaxf(ss, EPSF));
    p[lane]      = a * rn;
    p[lane + 32] = b * rn;
}

// ---------------- sequential gated delta-rule scan (128 thr: rows split 2-way) -----
__global__ __launch_bounds__(128)
void scan_kernel2(const float* __restrict__ Q, const float* __restrict__ K,
                  const float* __restrict__ V, const float* __restrict__ A,
                  const float* __restrict__ Beta,
                  float* __restrict__ O, float* __restrict__ Sout)
{
    const int bh = blockIdx.x;
    const int b = bh / HH, h = bh % HH;
    const int tid  = threadIdx.x;
    const int j    = tid & 63;
    const int half = tid >> 6;

    __shared__ float sq[2][64], sk[2][64], sa[2][64];
    __shared__ float kred[2][64];
    __shared__ float ored[2][2][64];

    float S[32];
#pragma unroll
    for (int i = 0; i < 32; i++) S[i] = 0.0f;

    const size_t base0 = ((size_t)b*TT)*DD + h*64;

    if (half == 0) { sq[0][j] = Q[base0 + j]; sk[0][j] = K[base0 + j]; }
    else           { sa[0][j] = A[base0 + j]; }
    float vj  = V[base0 + j];
    float bta = Beta[((size_t)b*TT)*HH + h];
    __syncthreads();

    for (int t = 0; t < TT; t++) {
        const int cur = t & 1, nxt = cur ^ 1;
        float vn = 0.0f, btan = 0.0f;
        if (t + 1 < TT) {
            size_t bs = base0 + (size_t)(t+1)*DD;
            if (half == 0) { sq[nxt][j] = Q[bs + j]; sk[nxt][j] = K[bs + j]; }
            else           { sa[nxt][j] = A[bs + j]; }
            vn   = V[bs + j];
            btan = Beta[((size_t)b*TT + (t+1))*HH + h];
        }

        const float* ka = &sk[cur][half*32];
        const float* aa = &sa[cur][half*32];
        float p0 = 0.f, p1 = 0.f;
#pragma unroll
        for (int i = 0; i < 32; i += 2) {
            S[i]   *= aa[i];   p0 = fmaf(ka[i],   S[i],   p0);
            S[i+1] *= aa[i+1]; p1 = fmaf(ka[i+1], S[i+1], p1);
        }
        kred[half][j] = p0 + p1;
        __syncthreads();

        float kts = kred[0][j] + kred[1][j];
        float dlt = bta * (vj - kts);

        const float* qa = &sq[cur][half*32];
        float o0 = 0.f, o1 = 0.f;
#pragma unroll
        for (int i = 0; i < 32; i += 2) {
            S[i]   = fmaf(ka[i],   dlt, S[i]);   o0 = fmaf(S[i],   qa[i],   o0);
            S[i+1] = fmaf(ka[i+1], dlt, S[i+1]); o1 = fmaf(S[i+1], qa[i+1], o1);
        }
        ored[cur][half][j] = o0 + o1;
        __syncthreads();

        if (half == 0)
            O[((size_t)b*TT + t)*DD + h*64 + j] = ored[cur][0][j] + ored[cur][1][j];

        vj = vn; bta = btan;
    }

#pragma unroll
    for (int i = 0; i < 32; i++)
        Sout[(size_t)bh*DKV*DKV + (size_t)(half*32 + i)*DKV + j] = S[i];
}

// ---------------- headwise RMSNorm + gate, emits bf16 hi/lo ------------------------
__global__ __launch_bounds__(256)
void normgate_split(const float* __restrict__ O, const float* __restrict__ rms_w,
                    const float* __restrict__ gate,
                    __nv_bfloat16* __restrict__ oh, __nv_bfloat16* __restrict__ ol)
{
    int row = blockIdx.x*4 + (threadIdx.x >> 6);
    int j   = threadIdx.x & 63;
    int h   = row % HH;

    float v = O[(size_t)row*64 + j];
    float ss = v*v;
#pragma unroll
    for (int o = 16; o; o >>= 1) ss += __shfl_xor_sync(0xFFFFFFFFu, ss, o);

    __shared__ float part[8];
    if ((threadIdx.x & 31) == 0) part[threadIdx.x >> 5] = ss;
    __syncthreads();
    int w0 = (threadIdx.x >> 6) * 2;
    float tot = part[w0] + part[w0 + 1];

    float rn  = rsqrtf(tot * (1.0f/64.0f) + EPSF);
    float val = v * rn * rms_w[h*64 + j] * gate[row];
    __nv_bfloat16 hh = __float2bfloat16(val);
    size_t idx = (size_t)row*64 + j;
    oh[idx] = hh;
    ol[idx] = __float2bfloat16(val - __bfloat162float(hh));
}

// ---------------- launch -----------------------------------------------------------
extern "C" void kernel_launch(void* const* d_in, const int* in_sizes, int n_in,
                              void* d_out, int out_size)
{
    const float* x       = (const float*)d_in[0];
    const float* conv_qw = (const float*)d_in[1];
    const float* conv_qb = (const float*)d_in[2];
    const float* conv_kw = (const float*)d_in[3];
    const float* conv_kb = (const float*)d_in[4];
    const float* conv_vw = (const float*)d_in[5];
    const float* conv_vb = (const float*)d_in[6];
    const float* Wq      = (const float*)d_in[7];
    const float* bq      = (const float*)d_in[8];
    const float* Wk      = (const float*)d_in[9];
    const float* bk      = (const float*)d_in[10];
    const float* Wv      = (const float*)d_in[11];
    const float* bv      = (const float*)d_in[12];
    const float* W_ad    = (const float*)d_in[13];
    const float* b_ad    = (const float*)d_in[14];
    const float* W_au    = (const float*)d_in[15];
    const float* b_au    = (const float*)d_in[16];
    const float* W_beta  = (const float*)d_in[17];
    const float* b_beta  = (const float*)d_in[18];
    const float* rms_w   = (const float*)d_in[19];
    const float* W_gd    = (const float*)d_in[20];
    const float* b_gd    = (const float*)d_in[21];
    const float* W_gu    = (const float*)d_in[22];
    const float* b_gu    = (const float*)d_in[23];
    const float* Wo      = (const float*)d_in[24];
    const float* bo      = (const float*)d_in[25];

    float* out = (float*)d_out;
    float* y = out;
    const size_t y_elems = (size_t)MTOK * DD;
    const size_t s_elems = (size_t)BH * DKV * DKV;
    float* Sout = out + ((size_t)out_size >= y_elems + s_elems
                         ? (size_t)out_size - s_elems : y_elems);

    float *Qp, *Kp, *Vp, *Al, *Op, *hA, *hG, *Bt, *Gt;
    cudaGetSymbolAddress((void**)&Qp, g_Q);
    cudaGetSymbolAddress((void**)&Kp, g_K);
    cudaGetSymbolAddress((void**)&Vp, g_V);
    cudaGetSymbolAddress((void**)&Al, g_alpha);
    cudaGetSymbolAddress((void**)&Op, g_O);
    cudaGetSymbolAddress((void**)&hA, g_hidA);
    cudaGetSymbolAddress((void**)&hG, g_hidG);
    cudaGetSymbolAddress((void**)&Bt, g_beta);
    cudaGetSymbolAddress((void**)&Gt, g_gate);

    __nv_bfloat16 *qxh,*qxl,*kxh,*kxl,*vxh,*vxl,*oh,*ol;
    __nv_bfloat16 *wqh,*wql,*wkh,*wkl,*wvh,*wvl,*woh,*wol;
    cudaGetSymbolAddress((void**)&qxh, g_qxh); cudaGetSymbolAddress((void**)&qxl, g_qxl);
    cudaGetSymbolAddress((void**)&kxh, g_kxh); cudaGetSymbolAddress((void**)&kxl, g_kxl);
    cudaGetSymbolAddress((void**)&vxh, g_vxh); cudaGetSymbolAddress((void**)&vxl, g_vxl);
    cudaGetSymbolAddress((void**)&oh,  g_oh);  cudaGetSymbolAddress((void**)&ol,  g_ol);
    cudaGetSymbolAddress((void**)&wqh, g_wqh); cudaGetSymbolAddress((void**)&wql, g_wql);
    cudaGetSymbolAddress((void**)&wkh, g_wkh); cudaGetSymbolAddress((void**)&wkl, g_wkl);
    cudaGetSymbolAddress((void**)&wvh, g_wvh); cudaGetSymbolAddress((void**)&wvl, g_wvl);
    cudaGetSymbolAddress((void**)&woh, g_woh); cudaGetSymbolAddress((void**)&wol, g_wol);

    cudaFuncSetAttribute(hgemm, cudaFuncAttributeMaxDynamicSharedMemorySize, HG_SMEM);

    // 0) weight transpose + bf16 split
    dim3 wgrid(DD/32, DD/32), wblk(32, 32);
    wsplit<<<wgrid, wblk>>>(Wq, wqh, wql);
    wsplit<<<wgrid, wblk>>>(Wk, wkh, wkl);
    wsplit<<<wgrid, wblk>>>(Wv, wvh, wvl);
    wsplit<<<wgrid, wblk>>>(Wo, woh, wol);

    // 1) causal depthwise convs + SiLU -> bf16 hi/lo
    conv_silu_split<<<(MTOK*DD + 255)/256, 256>>>(x, conv_qw, conv_qb,
                                                  conv_kw, conv_kb, conv_vw, conv_vb);

    // 2) Q/K/V projections on tensor cores (bf16 split, fp32 accumulate)
    dim3 tgrid(DD/128, MTOK/128);
    hgemm<<<tgrid, 256, HG_SMEM>>>(qxh, qxl, wqh, wql, bq, Qp, DD);
    hgemm<<<tgrid, 256, HG_SMEM>>>(kxh, kxl, wkh, wkl, bk, Kp, DD);
    hgemm<<<tgrid, 256, HG_SMEM>>>(vxh, vxl, wvh, wvl, bv, Vp, DD);

    // 3) L2 norm per (token, head) 64-group
    int ngroups = MTOK * HH;
    int l2blocks = (ngroups*32 + 255)/256;
    l2norm_kernel<<<l2blocks, 256>>>(Qp, ngroups);
    l2norm_kernel<<<l2blocks, 256>>>(Kp, ngroups);

    // 4) alpha = sigmoid(silu(x@W_ad+b_ad) @ W_au + b_au)
    gemm_small<1><<<dim3(1, MTOK/64), 256>>>(x, W_ad, b_ad, hA, MTOK, RR, DD);
    gemm128<2><<<dim3(DD/128, MTOK/128), 256>>>(hA, W_au, b_au, Al, MTOK, DD, RR);

    // 5) beta, gate
    gemm_small<2><<<dim3(1, MTOK/64), 256>>>(x, W_beta, b_beta, Bt, MTOK, HH, DD);
    gemm_small<1><<<dim3(1, MTOK/64), 256>>>(x, W_gd, b_gd, hG, MTOK, RR, DD);
    gemm_small<2><<<dim3(1, MTOK/64), 256>>>(hG, W_gu, b_gu, Gt, MTOK, HH, RR);

    // 6) sequential delta-rule scan (emits O and S_final)
    scan_kernel2<<<BH, 128>>>(Qp, Kp, Vp, Al, Bt, Op, Sout);

    // 7) RMSNorm + gate -> bf16 hi/lo
    normgate_split<<<(MTOK*HH)/4, 256>>>(Op, rms_w, Gt, oh, ol);

    // 8) y = O @ Wo + bo  (tensor cores)
    hgemm<<<tgrid, 256, HG_SMEM>>>(oh, ol, woh, wol, bo, y, DD);
}

// round 4
// speedup vs baseline: 1.6509x; 1.3388x over previous
#include <cuda_runtime.h>
#include <cuda_bf16.h>
#include <math.h>
#include <stdint.h>

// ---------------- problem constants ----------------
#define BB 4
#define TT 2048
#define DD 1024
#define HH 16
#define DKV 64
#define RR 64
#define KSZ 4
#define BH (BB*HH)      // 64
#define MTOK (BB*TT)    // 8192
#define EPSF 1e-6f

// ---------------- scratch (no cudaMalloc allowed) ----------------
__device__ __nv_bfloat16 g_qxh[MTOK*DD], g_qxl[MTOK*DD];
__device__ __nv_bfloat16 g_kxh[MTOK*DD], g_kxl[MTOK*DD];
__device__ __nv_bfloat16 g_vxh[MTOK*DD], g_vxl[MTOK*DD];
__device__ __nv_bfloat16 g_oh [MTOK*DD], g_ol [MTOK*DD];
__device__ __nv_bfloat16 g_wqh[DD*DD], g_wql[DD*DD];
__device__ __nv_bfloat16 g_wkh[DD*DD], g_wkl[DD*DD];
__device__ __nv_bfloat16 g_wvh[DD*DD], g_wvl[DD*DD];
__device__ __nv_bfloat16 g_woh[DD*DD], g_wol[DD*DD];
__device__ float g_Q [MTOK*DD];
__device__ float g_K [MTOK*DD];
__device__ float g_V [MTOK*DD];
__device__ float g_alpha[MTOK*DD];
__device__ float g_O [MTOK*DD];
__device__ float g_hidA[MTOK*RR];
__device__ float g_hidG[MTOK*RR];
__device__ float g_beta[MTOK*HH];
__device__ float g_gate[MTOK*HH];

__device__ __forceinline__ float sigmoidf_(float v){ return 1.0f/(1.0f+expf(-v)); }
__device__ __forceinline__ float siluf_(float v){ return v/(1.0f+expf(-v)); }

// ---------------- PTX helpers (baseline ISA only; NO sm_100a features) -------------
__device__ __forceinline__ uint32_t smem_u32(const void* p){
    uint32_t a;
    asm("{ .reg .u64 t; cvta.to.shared.u64 t, %1; cvt.u32.u64 %0, t; }" : "=r"(a) : "l"(p));
    return a;
}
#define CP_COMMIT() asm volatile("cp.async.commit_group;" ::: "memory")
#define CP_WAIT2()  asm volatile("cp.async.wait_group 2;" ::: "memory")
__device__ __forceinline__ void cp16(uint32_t dst, const void* src){
    asm volatile("cp.async.cg.shared.global [%0], [%1], 16;" :: "r"(dst), "l"(src) : "memory");
}
__device__ __forceinline__ void ldm4(uint32_t* r, uint32_t addr){
    asm volatile("ldmatrix.sync.aligned.m8n8.x4.shared.b16 {%0,%1,%2,%3}, [%4];"
        : "=r"(r[0]), "=r"(r[1]), "=r"(r[2]), "=r"(r[3]) : "r"(addr));
}
__device__ __forceinline__ void mma16816(float* d, const uint32_t* a, const uint32_t* b){
    asm volatile("mma.sync.aligned.m16n8k16.row.col.f32.bf16.bf16.f32 "
        "{%0,%1,%2,%3}, {%4,%5,%6,%7}, {%8,%9}, {%0,%1,%2,%3};"
        : "+f"(d[0]), "+f"(d[1]), "+f"(d[2]), "+f"(d[3])
        : "r"(a[0]), "r"(a[1]), "r"(a[2]), "r"(a[3]), "r"(b[0]), "r"(b[1]));
}

// ---------------- conv + SiLU, emits bf16 hi/lo splits ----------------
__global__ void conv_silu_split(const float* __restrict__ x,
                                const float* __restrict__ wq, const float* __restrict__ bq,
                                const float* __restrict__ wk, const float* __restrict__ bk,
                                const float* __restrict__ wv, const float* __restrict__ bv)
{
    int idx = blockIdx.x*blockDim.x + threadIdx.x;
    if (idx >= MTOK*DD) return;
    int d = idx % DD;
    int t = (idx / DD) % TT;
    int b = idx / (DD*TT);

    float xs[KSZ];
#pragma unroll
    for (int j = 0; j < KSZ; j++) {
        int tt = t - (KSZ-1) + j;
        xs[j] = (tt >= 0) ? x[((size_t)b*TT + tt)*DD + d] : 0.0f;
    }
    float aq = bq[d], ak = bk[d], av = bv[d];
#pragma unroll
    for (int j = 0; j < KSZ; j++) {
        aq = fmaf(xs[j], wq[d*KSZ + j], aq);
        ak = fmaf(xs[j], wk[d*KSZ + j], ak);
        av = fmaf(xs[j], wv[d*KSZ + j], av);
    }
    float q = siluf_(aq), k = siluf_(ak), v = siluf_(av);
    __nv_bfloat16 h;
    h = __float2bfloat16(q); g_qxh[idx] = h; g_qxl[idx] = __float2bfloat16(q - __bfloat162float(h));
    h = __float2bfloat16(k); g_kxh[idx] = h; g_kxl[idx] = __float2bfloat16(k - __bfloat162float(h));
    h = __float2bfloat16(v); g_vxh[idx] = h; g_vxl[idx] = __float2bfloat16(v - __bfloat162float(h));
}

// ---------------- W [K,N] f32 -> Wt hi/lo [N,K] bf16 (transpose + split) -----------
__global__ void wsplit(const float* __restrict__ W,
                       __nv_bfloat16* __restrict__ Th, __nv_bfloat16* __restrict__ Tl)
{
    __shared__ float tile[32][33];
    int k = blockIdx.y*32 + threadIdx.y;
    int n = blockIdx.x*32 + threadIdx.x;
    tile[threadIdx.y][threadIdx.x] = W[(size_t)k*DD + n];
    __syncthreads();
    int n2 = blockIdx.x*32 + threadIdx.y;
    int k2 = blockIdx.y*32 + threadIdx.x;
    float v = tile[threadIdx.x][threadIdx.y];
    __nv_bfloat16 h = __float2bfloat16(v);
    Th[(size_t)n2*DD + k2] = h;
    Tl[(size_t)n2*DD + k2] = __float2bfloat16(v - __bfloat162float(h));
}

// ---------------- HMMA bf16-split GEMM ----------------------------------------------
#define STAGES 4
#define AROWB 80
#define STAGE_A_BYTES (128*AROWB)
#define STAGE_BYTES   (2*STAGE_A_BYTES)
#define HG_SMEM       (STAGES*STAGE_BYTES)
#define HG_NIT 96

__global__ __launch_bounds__(256)
void hgemm(const __nv_bfloat16* __restrict__ Ahp, const __nv_bfloat16* __restrict__ Alp,
           const __nv_bfloat16* __restrict__ Bhp, const __nv_bfloat16* __restrict__ Blp,
           const float* __restrict__ bias, float* __restrict__ C, int N_)
{
    extern __shared__ char smem[];
    uint32_t sb = smem_u32(smem);
    const int tid = threadIdx.x;
    const int wid = tid >> 5, lane = tid & 31;
    const int warp_m = wid >> 2, warp_n = wid & 3;
    const int m0 = blockIdx.y << 7, n0 = blockIdx.x << 7;

    float acc[4][4][4];
#pragma unroll
    for (int i = 0; i < 4; i++)
#pragma unroll
        for (int j = 0; j < 4; j++)
#pragma unroll
            for (int k = 0; k < 4; k++) acc[i][j][k] = 0.0f;

    const int lrow = tid >> 1;
    const int lcb  = (tid & 1) * 2;

    auto load_stage = [&](int it) {
        int seg = it >> 5;
        int kk  = (it & 31) << 5;
        const __nv_bfloat16* A = (seg == 2) ? Alp : Ahp;
        const __nv_bfloat16* B = (seg == 1) ? Blp : Bhp;
        uint32_t st = sb + (uint32_t)(it & (STAGES-1)) * STAGE_BYTES;
        const __nv_bfloat16* ga = A + (size_t)(m0 + lrow)*DD + kk + lcb*8;
        uint32_t da = st + lrow*AROWB + lcb*16;
        cp16(da,      ga);
        cp16(da + 16, ga + 8);
        const __nv_bfloat16* gb = B + (size_t)(n0 + lrow)*DD + kk + lcb*8;
        uint32_t db = st + STAGE_A_BYTES + lrow*AROWB + lcb*16;
        cp16(db,      gb);
        cp16(db + 16, gb + 8);
        CP_COMMIT();
    };

    load_stage(0); load_stage(1); load_stage(2);

    const uint32_t a_row = warp_m*64 + (lane & 15);
    const uint32_t a_col = (lane >> 4) * 16;
    const uint32_t b_row = warp_n*32 + (lane & 7) + ((lane >> 4) & 1) * 8;
    const uint32_t b_col = ((lane >> 3) & 1) * 16;

    for (int i = 0; i < HG_NIT; i++) {
        CP_WAIT2();
        __syncthreads();
        int j = i + 3;
        if (j < HG_NIT) load_stage(j); else CP_COMMIT();

        uint32_t st = sb + (uint32_t)(i & (STAGES-1)) * STAGE_BYTES;
#pragma unroll
        for (int ks = 0; ks < 2; ks++) {
            uint32_t afr[4][4], bfr[2][4];
            uint32_t abase = st + a_row*AROWB + ks*32 + a_col;
#pragma unroll
            for (int mf = 0; mf < 4; mf++) ldm4(afr[mf], abase + mf*(16*AROWB));
            uint32_t bbase = st + STAGE_A_BYTES + b_row*AROWB + ks*32 + b_col;
#pragma unroll
            for (int np = 0; np < 2; np++) ldm4(bfr[np], bbase + np*(16*AROWB));
#pragma unroll
            for (int mf = 0; mf < 4; mf++)
#pragma unroll
                for (int nf = 0; nf < 4; nf++)
                    mma16816(acc[mf][nf], afr[mf], &bfr[nf >> 1][(nf & 1) * 2]);
        }
    }

    const int trow = lane >> 2, tcol = (lane & 3) * 2;
#pragma unroll
    for (int mf = 0; mf < 4; mf++) {
        int r = m0 + warp_m*64 + mf*16 + trow;
#pragma unroll
        for (int nf = 0; nf < 4; nf++) {
            int c = n0 + warp_n*32 + nf*8 + tcol;
            float b0 = bias[c], b1 = bias[c+1];
            float* p0 = C + (size_t)r*N_ + c;
            float* p1 = C + (size_t)(r+8)*N_ + c;
            p0[0] = acc[mf][nf][0] + b0; p0[1] = acc[mf][nf][1] + b1;
            p1[0] = acc[mf][nf][2] + b0; p1[1] = acc[mf][nf][3] + b1;
        }
    }
}

// ---------------- fp32 SGEMM 128x128 (alpha-up, K=64) ------------------------------
template<int ACT>
__global__ __launch_bounds__(256)
void gemm128(const float* __restrict__ A, const float* __restrict__ W,
             const float* __restrict__ bias, float* __restrict__ C,
             int M, int N, int K)
{
    __shared__ float As[8][128];
    __shared__ float Bs[8][128];

    const int tid = threadIdx.x;
    const int m0 = blockIdx.y * 128;
    const int n0 = blockIdx.x * 128;
    const int ty = tid >> 4;
    const int tx = tid & 15;
    const int arow = tid >> 1;
    const int ak   = (tid & 1) * 4;
    const int brow = tid >> 5;
    const int bcol = (tid & 31) * 4;

    float acc[8][8];
#pragma unroll
    for (int i = 0; i < 8; i++)
#pragma unroll
        for (int j = 0; j < 8; j++) acc[i][j] = 0.0f;

    for (int k0 = 0; k0 < K; k0 += 8) {
        float4 a4 = *reinterpret_cast<const float4*>(&A[(size_t)(m0 + arow)*K + k0 + ak]);
        float4 b4 = *reinterpret_cast<const float4*>(&W[(size_t)(k0 + brow)*N + n0 + bcol]);
        __syncthreads();
        As[ak+0][arow] = a4.x; As[ak+1][arow] = a4.y;
        As[ak+2][arow] = a4.z; As[ak+3][arow] = a4.w;
        *reinterpret_cast<float4*>(&Bs[brow][bcol]) = b4;
        __syncthreads();
#pragma unroll
        for (int k = 0; k < 8; k++) {
            float ra[8], rb[8];
#pragma unroll
            for (int i = 0; i < 8; i++) ra[i] = As[k][ty*8 + i];
#pragma unroll
            for (int i = 0; i < 8; i++) rb[i] = Bs[k][tx*8 + i];
#pragma unroll
            for (int i = 0; i < 8; i++)
#pragma unroll
                for (int j = 0; j < 8; j++)
                    acc[i][j] = fmaf(ra[i], rb[j], acc[i][j]);
        }
    }

#pragma unroll
    for (int i = 0; i < 8; i++) {
        int m = m0 + ty*8 + i;
#pragma unroll
        for (int j = 0; j < 8; j++) {
            int n = n0 + tx*8 + j;
            float c = acc[i][j] + bias[n];
            if (ACT == 1) c = siluf_(c);
            else if (ACT == 2) c = sigmoidf_(c);
            C[(size_t)m*N + n] = c;
        }
    }
}

// ---------------- small SGEMM (beta/gate/alpha-down) --------------------------------
template<int ACT>
__global__ __launch_bounds__(256)
void gemm_small(const float* __restrict__ A, const float* __restrict__ W,
                const float* __restrict__ bias, float* __restrict__ C,
                int M, int N, int K)
{
    __shared__ float As[16][64];
    __shared__ float Bs[16][64];

    const int tid = threadIdx.x;
    const int m0 = blockIdx.y * 64;
    const int n0 = blockIdx.x * 64;
    const int ty = tid >> 4, tx = tid & 15;

    float acc[4][4];
#pragma unroll
    for (int i = 0; i < 4; i++)
#pragma unroll
        for (int j = 0; j < 4; j++) acc[i][j] = 0.0f;

    const int r  = tid >> 2,  c  = (tid & 3)  * 4;
    const int r2 = tid >> 4,  c2 = (tid & 15) * 4;

    for (int k0 = 0; k0 < K; k0 += 16) {
        __syncthreads();
#pragma unroll
        for (int i = 0; i < 4; i++) {
            int kk = k0 + c + i;
            int mm = m0 + r;
            As[c+i][r] = (kk < K && mm < M) ? A[(size_t)mm*K + kk] : 0.0f;
        }
#pragma unroll
        for (int i = 0; i < 4; i++) {
            int nn = n0 + c2 + i;
            int kk = k0 + r2;
            Bs[r2][c2+i] = (kk < K && nn < N) ? W[(size_t)kk*N + nn] : 0.0f;
        }
        __syncthreads();
#pragma unroll
        for (int k = 0; k < 16; k++) {
            float ra[4], rb[4];
#pragma unroll
            for (int i = 0; i < 4; i++) ra[i] = As[k][ty*4 + i];
#pragma unroll
            for (int i = 0; i < 4; i++) rb[i] = Bs[k][tx*4 + i];
#pragma unroll
            for (int i = 0; i < 4; i++)
#pragma unroll
                for (int j = 0; j < 4; j++)
                    acc[i][j] = fmaf(ra[i], rb[j], acc[i][j]);
        }
    }

#pragma unroll
    for (int i = 0; i < 4; i++) {
        int m = m0 + ty*4 + i;
        if (m >= M) continue;
#pragma unroll
        for (int j = 0; j < 4; j++) {
            int n = n0 + tx*4 + j;
            if (n >= N) continue;
            float cv = acc[i][j] + bias[n];
            if (ACT == 1) cv = siluf_(cv);
            else if (ACT == 2) cv = sigmoidf_(cv);
            C[(size_t)m*N + n] = cv;
        }
    }
}

// ---------------- L2 normalize each contiguous 64-group ----------------------------
__global__ void l2norm_kernel(float* __restrict__ Z, int ngroups)
{
    int warp = (blockIdx.x*blockDim.x + threadIdx.x) >> 5;
    int lane = threadIdx.x & 31;
    if (warp >= ngroups) return;
    float* p = Z + (size_t)warp * 64;
    float a = p[lane];
    float b = p[lane + 32];
    float ss = a*a + b*b;
#pragma unroll
    for (int o = 16; o; o >>= 1) ss += __shfl_xor_sync(0xFFFFFFFFu, ss, o);
    float rn = rsqrtf(fmaxf(ss, EPSF));
    p[lane]      = a * rn;
    p[lane + 32] = b * rn;
}

// ---------------- gated delta-rule scan, barrier-free -------------------------------
// 128 blocks = (head, column-half). 256 threads: lane bits[2:0] = row-eighth (8 rows),
// bits[7:3] = local column (32 per block). Reductions via 3x shfl.xor. Loads are
// register-pipelined 3 steps ahead (4 rotating buffers, unroll 4).
__global__ __launch_bounds__(256)
void scan_kernel3(const float* __restrict__ Q, const float* __restrict__ K,
                  const float* __restrict__ V, const float* __restrict__ A,
                  const float* __restrict__ Beta,
                  float* __restrict__ O, float* __restrict__ Sout)
{
    const int blk = blockIdx.x;          // 0..127
    const int bh  = blk >> 1, hf = blk & 1;
    const int b = bh / HH, h = bh % HH;
    const int tid = threadIdx.x;
    const int e   = tid & 7;             // row-eighth: rows e*8..e*8+7
    const int col = hf*32 + (tid >> 3);  // 0..63
    const int r0  = e * 8;

    const size_t base = ((size_t)b*TT)*DD + (size_t)h*64;
    const size_t bbase = (size_t)b*TT*HH + h;

    float S[8];
#pragma unroll
    for (int i = 0; i < 8; i++) S[i] = 0.0f;

    float4 kb[4][2], ab[4][2], qb[4][2];
    float  vb[4], bb[4];

#define SCAN_LOAD(t_, s_) do { \
    const float4* kp = reinterpret_cast<const float4*>(K + base + (size_t)(t_)*DD + r0); \
    const float4* ap = reinterpret_cast<const float4*>(A + base + (size_t)(t_)*DD + r0); \
    const float4* qp = reinterpret_cast<const float4*>(Q + base + (size_t)(t_)*DD + r0); \
    kb[s_][0] = kp[0]; kb[s_][1] = kp[1]; \
    ab[s_][0] = ap[0]; ab[s_][1] = ap[1]; \
    qb[s_][0] = qp[0]; qb[s_][1] = qp[1]; \
    vb[s_] = V[base + (size_t)(t_)*DD + col]; \
    bb[s_] = Beta[bbase + (size_t)(t_)*HH]; \
} while(0)

    SCAN_LOAD(0, 0); SCAN_LOAD(1, 1); SCAN_LOAD(2, 2);

#pragma unroll 4
    for (int t = 0; t < TT; t++) {
        const int s = t & 3;
        if (t + 3 < TT) SCAN_LOAD(t + 3, (t + 3) & 3);

        float k_[8], a_[8], q_[8];
        *reinterpret_cast<float4*>(&k_[0]) = kb[s][0];
        *reinterpret_cast<float4*>(&k_[4]) = kb[s][1];
        *reinterpret_cast<float4*>(&a_[0]) = ab[s][0];
        *reinterpret_cast<float4*>(&a_[4]) = ab[s][1];
        *reinterpret_cast<float4*>(&q_[0]) = qb[s][0];
        *reinterpret_cast<float4*>(&q_[4]) = qb[s][1];

        // phase 1: decay + k^T S partial over 8 rows
        float p0 = 0.f, p1 = 0.f;
#pragma unroll
        for (int i = 0; i < 8; i += 2) {
            S[i]   *= a_[i];   p0 = fmaf(k_[i],   S[i],   p0);
            S[i+1] *= a_[i+1]; p1 = fmaf(k_[i+1], S[i+1], p1);
        }
        float p = p0 + p1;
        p += __shfl_xor_sync(0xFFFFFFFFu, p, 1);
        p += __shfl_xor_sync(0xFFFFFFFFu, p, 2);
        p += __shfl_xor_sync(0xFFFFFFFFu, p, 4);

        float c = bb[s] * (vb[s] - p);

        // phase 2: rank-1 update + output partial
        float o0 = 0.f, o1 = 0.f;
#pragma unroll
        for (int i = 0; i < 8; i += 2) {
            S[i]   = fmaf(k_[i],   c, S[i]);   o0 = fmaf(S[i],   q_[i],   o0);
            S[i+1] = fmaf(k_[i+1], c, S[i+1]); o1 = fmaf(S[i+1], q_[i+1], o1);
        }
        float o = o0 + o1;
        o += __shfl_xor_sync(0xFFFFFFFFu, o, 1);
        o += __shfl_xor_sync(0xFFFFFFFFu, o, 2);
        o += __shfl_xor_sync(0xFFFFFFFFu, o, 4);

        if (e == 0)
            O[base + (size_t)t*DD + col] = o;
    }
#undef SCAN_LOAD

#pragma unroll
    for (int i = 0; i < 8; i++)
        Sout[(size_t)bh*DKV*DKV + (size_t)(r0 + i)*DKV + col] = S[i];
}

// ---------------- headwise RMSNorm + gate, emits bf16 hi/lo ------------------------
__global__ __launch_bounds__(256)
void normgate_split(const float* __restrict__ O, const float* __restrict__ rms_w,
                    const float* __restrict__ gate,
                    __nv_bfloat16* __restrict__ oh, __nv_bfloat16* __restrict__ ol)
{
    int row = blockIdx.x*4 + (threadIdx.x >> 6);
    int j   = threadIdx.x & 63;
    int h   = row % HH;

    float v = O[(size_t)row*64 + j];
    float ss = v*v;
#pragma unroll
    for (int o = 16; o; o >>= 1) ss += __shfl_xor_sync(0xFFFFFFFFu, ss, o);

    __shared__ float part[8];
    if ((threadIdx.x & 31) == 0) part[threadIdx.x >> 5] = ss;
    __syncthreads();
    int w0 = (threadIdx.x >> 6) * 2;
    float tot = part[w0] + part[w0 + 1];

    float rn  = rsqrtf(tot * (1.0f/64.0f) + EPSF);
    float val = v * rn * rms_w[h*64 + j] * gate[row];
    __nv_bfloat16 hh = __float2bfloat16(val);
    size_t idx = (size_t)row*64 + j;
    oh[idx] = hh;
    ol[idx] = __float2bfloat16(val - __bfloat162float(hh));
}

// ---------------- launch -----------------------------------------------------------
extern "C" void kernel_launch(void* const* d_in, const int* in_sizes, int n_in,
                              void* d_out, int out_size)
{
    const float* x       = (const float*)d_in[0];
    const float* conv_qw = (const float*)d_in[1];
    const float* conv_qb = (const float*)d_in[2];
    const float* conv_kw = (const float*)d_in[3];
    const float* conv_kb = (const float*)d_in[4];
    const float* conv_vw = (const float*)d_in[5];
    const float* conv_vb = (const float*)d_in[6];
    const float* Wq      = (const float*)d_in[7];
    const float* bq      = (const float*)d_in[8];
    const float* Wk      = (const float*)d_in[9];
    const float* bk      = (const float*)d_in[10];
    const float* Wv      = (const float*)d_in[11];
    const float* bv      = (const float*)d_in[12];
    const float* W_ad    = (const float*)d_in[13];
    const float* b_ad    = (const float*)d_in[14];
    const float* W_au    = (const float*)d_in[15];
    const float* b_au    = (const float*)d_in[16];
    const float* W_beta  = (const float*)d_in[17];
    const float* b_beta  = (const float*)d_in[18];
    const float* rms_w   = (const float*)d_in[19];
    const float* W_gd    = (const float*)d_in[20];
    const float* b_gd    = (const float*)d_in[21];
    const float* W_gu    = (const float*)d_in[22];
    const float* b_gu    = (const float*)d_in[23];
    const float* Wo      = (const float*)d_in[24];
    const float* bo      = (const float*)d_in[25];

    float* out = (float*)d_out;
    float* y = out;
    const size_t y_elems = (size_t)MTOK * DD;
    const size_t s_elems = (size_t)BH * DKV * DKV;
    float* Sout = out + ((size_t)out_size >= y_elems + s_elems
                         ? (size_t)out_size - s_elems : y_elems);

    float *Qp, *Kp, *Vp, *Al, *Op, *hA, *hG, *Bt, *Gt;
    cudaGetSymbolAddress((void**)&Qp, g_Q);
    cudaGetSymbolAddress((void**)&Kp, g_K);
    cudaGetSymbolAddress((void**)&Vp, g_V);
    cudaGetSymbolAddress((void**)&Al, g_alpha);
    cudaGetSymbolAddress((void**)&Op, g_O);
    cudaGetSymbolAddress((void**)&hA, g_hidA);
    cudaGetSymbolAddress((void**)&hG, g_hidG);
    cudaGetSymbolAddress((void**)&Bt, g_beta);
    cudaGetSymbolAddress((void**)&Gt, g_gate);

    __nv_bfloat16 *qxh,*qxl,*kxh,*kxl,*vxh,*vxl,*oh,*ol;
    __nv_bfloat16 *wqh,*wql,*wkh,*wkl,*wvh,*wvl,*woh,*wol;
    cudaGetSymbolAddress((void**)&qxh, g_qxh); cudaGetSymbolAddress((void**)&qxl, g_qxl);
    cudaGetSymbolAddress((void**)&kxh, g_kxh); cudaGetSymbolAddress((void**)&kxl, g_kxl);
    cudaGetSymbolAddress((void**)&vxh, g_vxh); cudaGetSymbolAddress((void**)&vxl, g_vxl);
    cudaGetSymbolAddress((void**)&oh,  g_oh);  cudaGetSymbolAddress((void**)&ol,  g_ol);
    cudaGetSymbolAddress((void**)&wqh, g_wqh); cudaGetSymbolAddress((void**)&wql, g_wql);
    cudaGetSymbolAddress((void**)&wkh, g_wkh); cudaGetSymbolAddress((void**)&wkl, g_wkl);
    cudaGetSymbolAddress((void**)&wvh, g_wvh); cudaGetSymbolAddress((void**)&wvl, g_wvl);
    cudaGetSymbolAddress((void**)&woh, g_woh); cudaGetSymbolAddress((void**)&wol, g_wol);

    cudaFuncSetAttribute(hgemm, cudaFuncAttributeMaxDynamicSharedMemorySize, HG_SMEM);

    // 0) weight transpose + bf16 split
    dim3 wgrid(DD/32, DD/32), wblk(32, 32);
    wsplit<<<wgrid, wblk>>>(Wq, wqh, wql);
    wsplit<<<wgrid, wblk>>>(Wk, wkh, wkl);
    wsplit<<<wgrid, wblk>>>(Wv, wvh, wvl);
    wsplit<<<wgrid, wblk>>>(Wo, woh, wol);

    // 1) causal depthwise convs + SiLU -> bf16 hi/lo
    conv_silu_split<<<(MTOK*DD + 255)/256, 256>>>(x, conv_qw, conv_qb,
                                                  conv_kw, conv_kb, conv_vw, conv_vb);

    // 2) Q/K/V projections on tensor cores (bf16 split, fp32 accumulate)
    dim3 tgrid(DD/128, MTOK/128);
    hgemm<<<tgrid, 256, HG_SMEM>>>(qxh, qxl, wqh, wql, bq, Qp, DD);
    hgemm<<<tgrid, 256, HG_SMEM>>>(kxh, kxl, wkh, wkl, bk, Kp, DD);
    hgemm<<<tgrid, 256, HG_SMEM>>>(vxh, vxl, wvh, wvl, bv, Vp, DD);

    // 3) L2 norm per (token, head) 64-group
    int ngroups = MTOK * HH;
    int l2blocks = (ngroups*32 + 255)/256;
    l2norm_kernel<<<l2blocks, 256>>>(Qp, ngroups);
    l2norm_kernel<<<l2blocks, 256>>>(Kp, ngroups);

    // 4) alpha = sigmoid(silu(x@W_ad+b_ad) @ W_au + b_au)
    gemm_small<1><<<dim3(1, MTOK/64), 256>>>(x, W_ad, b_ad, hA, MTOK, RR, DD);
    gemm128<2><<<dim3(DD/128, MTOK/128), 256>>>(hA, W_au, b_au, Al, MTOK, DD, RR);

    // 5) beta, gate
    gemm_small<2><<<dim3(1, MTOK/64), 256>>>(x, W_beta, b_beta, Bt, MTOK, HH, DD);
    gemm_small<1><<<dim3(1, MTOK/64), 256>>>(x, W_gd, b_gd, hG, MTOK, RR, DD);
    gemm_small<2><<<dim3(1, MTOK/64), 256>>>(hG, W_gu, b_gu, Gt, MTOK, HH, RR);

    // 6) barrier-free delta-rule scan (emits O and S_final)
    scan_kernel3<<<2*BH, 256>>>(Qp, Kp, Vp, Al, Bt, Op, Sout);

    // 7) RMSNorm + gate -> bf16 hi/lo
    normgate_split<<<(MTOK*HH)/4, 256>>>(Op, rms_w, Gt, oh, ol);

    // 8) y = O @ Wo + bo  (tensor cores)
    hgemm<<<tgrid, 256, HG_SMEM>>>(oh, ol, woh, wol, bo, y, DD);
}

// round 5
// speedup vs baseline: 1.7830x; 1.0800x over previous
#include <cuda_runtime.h>
#include <cuda_bf16.h>
#include <math.h>
#include <stdint.h>

// ---------------- problem constants ----------------
#define BB 4
#define TT 2048
#define DD 1024
#define HH 16
#define DKV 64
#define RR 64
#define KSZ 4
#define BH (BB*HH)      // 64
#define MTOK (BB*TT)    // 8192
#define EPSF 1e-6f

// ---------------- scratch (no cudaMalloc allowed) ----------------
__device__ __nv_bfloat16 g_qxh[MTOK*DD], g_qxl[MTOK*DD];
__device__ __nv_bfloat16 g_kxh[MTOK*DD], g_kxl[MTOK*DD];
__device__ __nv_bfloat16 g_vxh[MTOK*DD], g_vxl[MTOK*DD];
__device__ __nv_bfloat16 g_oh [MTOK*DD], g_ol [MTOK*DD];
__device__ __nv_bfloat16 g_wqh[DD*DD], g_wql[DD*DD];
__device__ __nv_bfloat16 g_wkh[DD*DD], g_wkl[DD*DD];
__device__ __nv_bfloat16 g_wvh[DD*DD], g_wvl[DD*DD];
__device__ __nv_bfloat16 g_woh[DD*DD], g_wol[DD*DD];
__device__ float g_Q [MTOK*DD];
__device__ float g_K [MTOK*DD];
__device__ float g_V [MTOK*DD];
__device__ float g_alpha[MTOK*DD];
__device__ float g_O [MTOK*DD];
__device__ float g_hidA[MTOK*RR];
__device__ float g_hidG[MTOK*RR];
__device__ float g_beta[MTOK*HH];
__device__ float g_gate[MTOK*HH];

__device__ __forceinline__ float sigmoidf_(float v){ return 1.0f/(1.0f+expf(-v)); }
__device__ __forceinline__ float siluf_(float v){ return v/(1.0f+expf(-v)); }

// ---------------- PTX helpers (baseline ISA only; NO sm_100a features) -------------
__device__ __forceinline__ uint32_t smem_u32(const void* p){
    uint32_t a;
    asm("{ .reg .u64 t; cvta.to.shared.u64 t, %1; cvt.u32.u64 %0, t; }" : "=r"(a) : "l"(p));
    return a;
}
#define CP_COMMIT() asm volatile("cp.async.commit_group;" ::: "memory")
#define CP_WAIT2()  asm volatile("cp.async.wait_group 2;" ::: "memory")
__device__ __forceinline__ void cp16(uint32_t dst, const void* src){
    asm volatile("cp.async.cg.shared.global [%0], [%1], 16;" :: "r"(dst), "l"(src) : "memory");
}
__device__ __forceinline__ void ldm4(uint32_t* r, uint32_t addr){
    asm volatile("ldmatrix.sync.aligned.m8n8.x4.shared.b16 {%0,%1,%2,%3}, [%4];"
        : "=r"(r[0]), "=r"(r[1]), "=r"(r[2]), "=r"(r[3]) : "r"(addr));
}
__device__ __forceinline__ void mma16816(float* d, const uint32_t* a, const uint32_t* b){
    asm volatile("mma.sync.aligned.m16n8k16.row.col.f32.bf16.bf16.f32 "
        "{%0,%1,%2,%3}, {%4,%5,%6,%7}, {%8,%9}, {%0,%1,%2,%3};"
        : "+f"(d[0]), "+f"(d[1]), "+f"(d[2]), "+f"(d[3])
        : "r"(a[0]), "r"(a[1]), "r"(a[2]), "r"(a[3]), "r"(b[0]), "r"(b[1]));
}

// ---------------- conv + SiLU, emits bf16 hi/lo splits ----------------
__global__ void conv_silu_split(const float* __restrict__ x,
                                const float* __restrict__ wq, const float* __restrict__ bq,
                                const float* __restrict__ wk, const float* __restrict__ bk,
                                const float* __restrict__ wv, const float* __restrict__ bv)
{
    int idx = blockIdx.x*blockDim.x + threadIdx.x;
    if (idx >= MTOK*DD) return;
    int d = idx % DD;
    int t = (idx / DD) % TT;
    int b = idx / (DD*TT);

    float xs[KSZ];
#pragma unroll
    for (int j = 0; j < KSZ; j++) {
        int tt = t - (KSZ-1) + j;
        xs[j] = (tt >= 0) ? x[((size_t)b*TT + tt)*DD + d] : 0.0f;
    }
    float aq = bq[d], ak = bk[d], av = bv[d];
#pragma unroll
    for (int j = 0; j < KSZ; j++) {
        aq = fmaf(xs[j], wq[d*KSZ + j], aq);
        ak = fmaf(xs[j], wk[d*KSZ + j], ak);
        av = fmaf(xs[j], wv[d*KSZ + j], av);
    }
    float q = siluf_(aq), k = siluf_(ak), v = siluf_(av);
    __nv_bfloat16 h;
    h = __float2bfloat16(q); g_qxh[idx] = h; g_qxl[idx] = __float2bfloat16(q - __bfloat162float(h));
    h = __float2bfloat16(k); g_kxh[idx] = h; g_kxl[idx] = __float2bfloat16(k - __bfloat162float(h));
    h = __float2bfloat16(v); g_vxh[idx] = h; g_vxl[idx] = __float2bfloat16(v - __bfloat162float(h));
}

// ---------------- 4 weights: [K,N] f32 -> [N,K] bf16 hi/lo (one launch) ------------
__global__ void wsplit_all(const float* __restrict__ W0, __nv_bfloat16* __restrict__ H0, __nv_bfloat16* __restrict__ L0,
                           const float* __restrict__ W1, __nv_bfloat16* __restrict__ H1, __nv_bfloat16* __restrict__ L1,
                           const float* __restrict__ W2, __nv_bfloat16* __restrict__ H2, __nv_bfloat16* __restrict__ L2,
                           const float* __restrict__ W3, __nv_bfloat16* __restrict__ H3, __nv_bfloat16* __restrict__ L3)
{
    const float* W; __nv_bfloat16 *Th, *Tl;
    switch (blockIdx.z) {
        case 0: W = W0; Th = H0; Tl = L0; break;
        case 1: W = W1; Th = H1; Tl = L1; break;
        case 2: W = W2; Th = H2; Tl = L2; break;
        default: W = W3; Th = H3; Tl = L3; break;
    }
    __shared__ float tile[32][33];
    int k = blockIdx.y*32 + threadIdx.y;
    int n = blockIdx.x*32 + threadIdx.x;
    tile[threadIdx.y][threadIdx.x] = W[(size_t)k*DD + n];
    __syncthreads();
    int n2 = blockIdx.x*32 + threadIdx.y;
    int k2 = blockIdx.y*32 + threadIdx.x;
    float v = tile[threadIdx.x][threadIdx.y];
    __nv_bfloat16 h = __float2bfloat16(v);
    Th[(size_t)n2*DD + k2] = h;
    Tl[(size_t)n2*DD + k2] = __float2bfloat16(v - __bfloat162float(h));
}

// ---------------- HMMA bf16-split GEMM, optional fused bias+L2norm epilogue --------
#define STAGES 4
#define AROWB 80
#define STAGE_A_BYTES (128*AROWB)
#define STAGE_BYTES   (2*STAGE_A_BYTES)
#define HG_SMEM       (STAGES*STAGE_BYTES)
#define HG_NIT 96

template<int DO_L2>
__global__ __launch_bounds__(256)
void hgemm(const __nv_bfloat16* __restrict__ Ahp, const __nv_bfloat16* __restrict__ Alp,
           const __nv_bfloat16* __restrict__ Bhp, const __nv_bfloat16* __restrict__ Blp,
           const float* __restrict__ bias, float* __restrict__ C, int N_)
{
    extern __shared__ char smem[];
    uint32_t sb = smem_u32(smem);
    const int tid = threadIdx.x;
    const int wid = tid >> 5, lane = tid & 31;
    const int warp_m = wid >> 2, warp_n = wid & 3;
    const int m0 = blockIdx.y << 7, n0 = blockIdx.x << 7;

    float acc[4][4][4];
#pragma unroll
    for (int i = 0; i < 4; i++)
#pragma unroll
        for (int j = 0; j < 4; j++)
#pragma unroll
            for (int k = 0; k < 4; k++) acc[i][j][k] = 0.0f;

    const int lrow = tid >> 1;
    const int lcb  = (tid & 1) * 2;

    auto load_stage = [&](int it) {
        int seg = it >> 5;
        int kk  = (it & 31) << 5;
        const __nv_bfloat16* A = (seg == 2) ? Alp : Ahp;
        const __nv_bfloat16* B = (seg == 1) ? Blp : Bhp;
        uint32_t st = sb + (uint32_t)(it & (STAGES-1)) * STAGE_BYTES;
        const __nv_bfloat16* ga = A + (size_t)(m0 + lrow)*DD + kk + lcb*8;
        uint32_t da = st + lrow*AROWB + lcb*16;
        cp16(da,      ga);
        cp16(da + 16, ga + 8);
        const __nv_bfloat16* gb = B + (size_t)(n0 + lrow)*DD + kk + lcb*8;
        uint32_t db = st + STAGE_A_BYTES + lrow*AROWB + lcb*16;
        cp16(db,      gb);
        cp16(db + 16, gb + 8);
        CP_COMMIT();
    };

    load_stage(0); load_stage(1); load_stage(2);

    const uint32_t a_row = warp_m*64 + (lane & 15);
    const uint32_t a_col = (lane >> 4) * 16;
    const uint32_t b_row = warp_n*32 + (lane & 7) + ((lane >> 4) & 1) * 8;
    const uint32_t b_col = ((lane >> 3) & 1) * 16;

    for (int i = 0; i < HG_NIT; i++) {
        CP_WAIT2();
        __syncthreads();
        int j = i + 3;
        if (j < HG_NIT) load_stage(j); else CP_COMMIT();

        uint32_t st = sb + (uint32_t)(i & (STAGES-1)) * STAGE_BYTES;
#pragma unroll
        for (int ks = 0; ks < 2; ks++) {
            uint32_t afr[4][4], bfr[2][4];
            uint32_t abase = st + a_row*AROWB + ks*32 + a_col;
#pragma unroll
            for (int mf = 0; mf < 4; mf++) ldm4(afr[mf], abase + mf*(16*AROWB));
            uint32_t bbase = st + STAGE_A_BYTES + b_row*AROWB + ks*32 + b_col;
#pragma unroll
            for (int np = 0; np < 2; np++) ldm4(bfr[np], bbase + np*(16*AROWB));
#pragma unroll
            for (int mf = 0; mf < 4; mf++)
#pragma unroll
                for (int nf = 0; nf < 4; nf++)
                    mma16816(acc[mf][nf], afr[mf], &bfr[nf >> 1][(nf & 1) * 2]);
        }
    }

    const int trow = lane >> 2, tcol = (lane & 3) * 2;

    // add bias into accumulators
#pragma unroll
    for (int nf = 0; nf < 4; nf++) {
        int c = n0 + warp_n*32 + nf*8 + tcol;
        float b0 = bias[c], b1 = bias[c+1];
#pragma unroll
        for (int mf = 0; mf < 4; mf++) {
            acc[mf][nf][0] += b0; acc[mf][nf][1] += b1;
            acc[mf][nf][2] += b0; acc[mf][nf][3] += b1;
        }
    }

    if (DO_L2) {
        // rowwise sum of squares within this warp's 32-col span (one 64-group half)
        float rs[8];              // rows: mf*2 + (0:+trow, 1:+trow+8)
#pragma unroll
        for (int mf = 0; mf < 4; mf++) {
            float s0 = 0.f, s1 = 0.f;
#pragma unroll
            for (int nf = 0; nf < 4; nf++) {
                s0 = fmaf(acc[mf][nf][0], acc[mf][nf][0], s0);
                s0 = fmaf(acc[mf][nf][1], acc[mf][nf][1], s0);
                s1 = fmaf(acc[mf][nf][2], acc[mf][nf][2], s1);
                s1 = fmaf(acc[mf][nf][3], acc[mf][nf][3], s1);
            }
            rs[mf*2]   = s0;
            rs[mf*2+1] = s1;
        }
#pragma unroll
        for (int r = 0; r < 8; r++) {
            rs[r] += __shfl_xor_sync(0xFFFFFFFFu, rs[r], 1);
            rs[r] += __shfl_xor_sync(0xFFFFFFFFu, rs[r], 2);
        }
        __syncthreads();                       // pipeline smem no longer needed
        float* sred = reinterpret_cast<float*>(smem);   // [4][128]
        if ((lane & 3) == 0) {
#pragma unroll
            for (int mf = 0; mf < 4; mf++) {
                int r = warp_m*64 + mf*16 + trow;
                sred[warp_n*128 + r]     = rs[mf*2];
                sred[warp_n*128 + r + 8] = rs[mf*2+1];
            }
        }
        __syncthreads();
        const int gp = (warp_n >> 1) * 2;      // partner pair base (0 or 2)
#pragma unroll
        for (int mf = 0; mf < 4; mf++) {
#pragma unroll
            for (int half = 0; half < 2; half++) {
                int r = warp_m*64 + mf*16 + trow + half*8;
                float tot = sred[gp*128 + r] + sred[(gp+1)*128 + r];
                float rn = rsqrtf(fmaxf(tot, EPSF));
                acc[mf][0][half*2]   *= rn; acc[mf][0][half*2+1] *= rn;
                acc[mf][1][half*2]   *= rn; acc[mf][1][half*2+1] *= rn;
                acc[mf][2][half*2]   *= rn; acc[mf][2][half*2+1] *= rn;
                acc[mf][3][half*2]   *= rn; acc[mf][3][half*2+1] *= rn;
            }
        }
    }

#pragma unroll
    for (int mf = 0; mf < 4; mf++) {
        int r = m0 + warp_m*64 + mf*16 + trow;
#pragma unroll
        for (int nf = 0; nf < 4; nf++) {
            int c = n0 + warp_n*32 + nf*8 + tcol;
            float* p0 = C + (size_t)r*N_ + c;
            float* p1 = C + (size_t)(r+8)*N_ + c;
            p0[0] = acc[mf][nf][0]; p0[1] = acc[mf][nf][1];
            p1[0] = acc[mf][nf][2]; p1[1] = acc[mf][nf][3];
        }
    }
}

// ---------------- fp32 SGEMM 128x128 (alpha-up, K=64, sigmoid) ---------------------
template<int ACT>
__global__ __launch_bounds__(256)
void gemm128(const float* __restrict__ A, const float* __restrict__ W,
             const float* __restrict__ bias, float* __restrict__ C,
             int M, int N, int K)
{
    __shared__ float As[8][128];
    __shared__ float Bs[8][128];

    const int tid = threadIdx.x;
    const int m0 = blockIdx.y * 128;
    const int n0 = blockIdx.x * 128;
    const int ty = tid >> 4;
    const int tx = tid & 15;
    const int arow = tid >> 1;
    const int ak   = (tid & 1) * 4;
    const int brow = tid >> 5;
    const int bcol = (tid & 31) * 4;

    float acc[8][8];
#pragma unroll
    for (int i = 0; i < 8; i++)
#pragma unroll
        for (int j = 0; j < 8; j++) acc[i][j] = 0.0f;

    for (int k0 = 0; k0 < K; k0 += 8) {
        float4 a4 = *reinterpret_cast<const float4*>(&A[(size_t)(m0 + arow)*K + k0 + ak]);
        float4 b4 = *reinterpret_cast<const float4*>(&W[(size_t)(k0 + brow)*N + n0 + bcol]);
        __syncthreads();
        As[ak+0][arow] = a4.x; As[ak+1][arow] = a4.y;
        As[ak+2][arow] = a4.z; As[ak+3][arow] = a4.w;
        *reinterpret_cast<float4*>(&Bs[brow][bcol]) = b4;
        __syncthreads();
#pragma unroll
        for (int k = 0; k < 8; k++) {
            float ra[8], rb[8];
#pragma unroll
            for (int i = 0; i < 8; i++) ra[i] = As[k][ty*8 + i];
#pragma unroll
            for (int i = 0; i < 8; i++) rb[i] = Bs[k][tx*8 + i];
#pragma unroll
            for (int i = 0; i < 8; i++)
#pragma unroll
                for (int j = 0; j < 8; j++)
                    acc[i][j] = fmaf(ra[i], rb[j], acc[i][j]);
        }
    }

#pragma unroll
    for (int i = 0; i < 8; i++) {
        int m = m0 + ty*8 + i;
#pragma unroll
        for (int j = 0; j < 8; j++) {
            int n = n0 + tx*8 + j;
            float c = acc[i][j] + bias[n];
            if (ACT == 1) c = siluf_(c);
            else if (ACT == 2) c = sigmoidf_(c);
            C[(size_t)m*N + n] = c;
        }
    }
}

// ---------------- fused x-projections: hA (silu, 64) | hG (silu, 64) | beta (sig,16)
// C144 = x @ [W_ad | W_gd | W_beta], one pass over x. 128 blocks x 256 thr.
__global__ __launch_bounds__(256)
void prep144(const float* __restrict__ x,
             const float* __restrict__ W_ad, const float* __restrict__ b_ad,
             const float* __restrict__ W_gd, const float* __restrict__ b_gd,
             const float* __restrict__ W_bt, const float* __restrict__ b_bt,
             float* __restrict__ hA, float* __restrict__ hG, float* __restrict__ Bt)
{
    __shared__ float Xs[16][68];
    __shared__ float Ws[16][144];

    const int tid = threadIdx.x;
    const int m0 = blockIdx.x * 64;
    const int ty = tid >> 4, tx = tid & 15;

    float acc[4][9];
#pragma unroll
    for (int i = 0; i < 4; i++)
#pragma unroll
        for (int j = 0; j < 9; j++) acc[i][j] = 0.0f;

    const int xrow = tid >> 2, xk = (tid & 3) * 4;
    const int wk = tid >> 4, wc = tid & 15;

    for (int k0 = 0; k0 < DD; k0 += 16) {
        __syncthreads();
        float4 xv = *reinterpret_cast<const float4*>(&x[(size_t)(m0 + xrow)*DD + k0 + xk]);
        Xs[xk+0][xrow] = xv.x; Xs[xk+1][xrow] = xv.y;
        Xs[xk+2][xrow] = xv.z; Xs[xk+3][xrow] = xv.w;
#pragma unroll
        for (int j = 0; j < 9; j++) {
            int c = wc + j*16;
            float w;
            if (c < 64)       w = W_ad[(size_t)(k0 + wk)*64 + c];
            else if (c < 128) w = W_gd[(size_t)(k0 + wk)*64 + (c - 64)];
            else              w = W_bt[(size_t)(k0 + wk)*16 + (c - 128)];
            Ws[wk][c] = w;
        }
        __syncthreads();
#pragma unroll
        for (int k = 0; k < 16; k++) {
            float ra[4], rb[9];
#pragma unroll
            for (int i = 0; i < 4; i++) ra[i] = Xs[k][ty*4 + i];
#pragma unroll
            for (int j = 0; j < 9; j++) rb[j] = Ws[k][tx + j*16];
#pragma unroll
            for (int i = 0; i < 4; i++)
#pragma unroll
                for (int j = 0; j < 9; j++)
                    acc[i][j] = fmaf(ra[i], rb[j], acc[i][j]);
        }
    }

#pragma unroll
    for (int i = 0; i < 4; i++) {
        int m = m0 + ty*4 + i;
#pragma unroll
        for (int j = 0; j < 9; j++) {
            int c = tx + j*16;
            float v = acc[i][j];
            if (c < 64)       hA[(size_t)m*64 + c]        = siluf_(v + b_ad[c]);
            else if (c < 128) hG[(size_t)m*64 + (c-64)]   = siluf_(v + b_gd[c-64]);
            else              Bt[(size_t)m*16 + (c-128)]  = sigmoidf_(v + b_bt[c-128]);
        }
    }
}

// ---------------- gate-up: gate = sigmoid(hidG @ W_gu + b_gu), N=16, K=64 ----------
__global__ __launch_bounds__(256)
void gateup(const float* __restrict__ hG, const float* __restrict__ W_gu,
            const float* __restrict__ b_gu, float* __restrict__ Gt)
{
    int gidx = blockIdx.x*256 + threadIdx.x;   // over MTOK*16
    int m = gidx >> 4, h = gidx & 15;
    const float* row = hG + (size_t)m*64;
    float s = b_gu[h];
#pragma unroll 8
    for (int i = 0; i < 64; i++) s = fmaf(row[i], W_gu[i*16 + h], s);
    Gt[gidx] = sigmoidf_(s);
}

// ---------------- gated delta-rule scan, barrier-free -------------------------------
__global__ __launch_bounds__(256)
void scan_kernel3(const float* __restrict__ Q, const float* __restrict__ K,
                  const float* __restrict__ V, const float* __restrict__ A,
                  const float* __restrict__ Beta,
                  float* __restrict__ O, float* __restrict__ Sout)
{
    const int blk = blockIdx.x;          // 0..127
    const int bh  = blk >> 1, hf = blk & 1;
    const int b = bh / HH, h = bh % HH;
    const int tid = threadIdx.x;
    const int e   = tid & 7;
    const int col = hf*32 + (tid >> 3);
    const int r0  = e * 8;

    const size_t base = ((size_t)b*TT)*DD + (size_t)h*64;
    const size_t bbase = (size_t)b*TT*HH + h;

    float S[8];
#pragma unroll
    for (int i = 0; i < 8; i++) S[i] = 0.0f;

    float4 kb[4][2], ab[4][2], qb[4][2];
    float  vb[4], bb[4];

#define SCAN_LOAD(t_, s_) do { \
    const float4* kp = reinterpret_cast<const float4*>(K + base + (size_t)(t_)*DD + r0); \
    const float4* ap = reinterpret_cast<const float4*>(A + base + (size_t)(t_)*DD + r0); \
    const float4* qp = reinterpret_cast<const float4*>(Q + base + (size_t)(t_)*DD + r0); \
    kb[s_][0] = kp[0]; kb[s_][1] = kp[1]; \
    ab[s_][0] = ap[0]; ab[s_][1] = ap[1]; \
    qb[s_][0] = qp[0]; qb[s_][1] = qp[1]; \
    vb[s_] = V[base + (size_t)(t_)*DD + col]; \
    bb[s_] = Beta[bbase + (size_t)(t_)*HH]; \
} while(0)

    SCAN_LOAD(0, 0); SCAN_LOAD(1, 1); SCAN_LOAD(2, 2);

#pragma unroll 4
    for (int t = 0; t < TT; t++) {
        const int s = t & 3;
        if (t + 3 < TT) SCAN_LOAD(t + 3, (t + 3) & 3);

        float k_[8], a_[8], q_[8];
        *reinterpret_cast<float4*>(&k_[0]) = kb[s][0];
        *reinterpret_cast<float4*>(&k_[4]) = kb[s][1];
        *reinterpret_cast<float4*>(&a_[0]) = ab[s][0];
        *reinterpret_cast<float4*>(&a_[4]) = ab[s][1];
        *reinterpret_cast<float4*>(&q_[0]) = qb[s][0];
        *reinterpret_cast<float4*>(&q_[4]) = qb[s][1];

        float p0 = 0.f, p1 = 0.f;
#pragma unroll
        for (int i = 0; i < 8; i += 2) {
            S[i]   *= a_[i];   p0 = fmaf(k_[i],   S[i],   p0);
            S[i+1] *= a_[i+1]; p1 = fmaf(k_[i+1], S[i+1], p1);
        }
        float p = p0 + p1;
        p += __shfl_xor_sync(0xFFFFFFFFu, p, 1);
        p += __shfl_xor_sync(0xFFFFFFFFu, p, 2);
        p += __shfl_xor_sync(0xFFFFFFFFu, p, 4);

        float c = bb[s] * (vb[s] - p);

        float o0 = 0.f, o1 = 0.f;
#pragma unroll
        for (int i = 0; i < 8; i += 2) {
            S[i]   = fmaf(k_[i],   c, S[i]);   o0 = fmaf(S[i],   q_[i],   o0);
            S[i+1] = fmaf(k_[i+1], c, S[i+1]); o1 = fmaf(S[i+1], q_[i+1], o1);
        }
        float o = o0 + o1;
        o += __shfl_xor_sync(0xFFFFFFFFu, o, 1);
        o += __shfl_xor_sync(0xFFFFFFFFu, o, 2);
        o += __shfl_xor_sync(0xFFFFFFFFu, o, 4);

        if (e == 0)
            O[base + (size_t)t*DD + col] = o;
    }
#undef SCAN_LOAD

#pragma unroll
    for (int i = 0; i < 8; i++)
        Sout[(size_t)bh*DKV*DKV + (size_t)(r0 + i)*DKV + col] = S[i];
}

// ---------------- headwise RMSNorm + gate, emits bf16 hi/lo ------------------------
__global__ __launch_bounds__(256)
void normgate_split(const float* __restrict__ O, const float* __restrict__ rms_w,
                    const float* __restrict__ gate,
                    __nv_bfloat16* __restrict__ oh, __nv_bfloat16* __restrict__ ol)
{
    int row = blockIdx.x*4 + (threadIdx.x >> 6);
    int j   = threadIdx.x & 63;
    int h   = row % HH;

    float v = O[(size_t)row*64 + j];
    float ss = v*v;
#pragma unroll
    for (int o = 16; o; o >>= 1) ss += __shfl_xor_sync(0xFFFFFFFFu, ss, o);

    __shared__ float part[8];
    if ((threadIdx.x & 31) == 0) part[threadIdx.x >> 5] = ss;
    __syncthreads();
    int w0 = (threadIdx.x >> 6) * 2;
    float tot = part[w0] + part[w0 + 1];

    float rn  = rsqrtf(tot * (1.0f/64.0f) + EPSF);
    float val = v * rn * rms_w[h*64 + j] * gate[row];
    __nv_bfloat16 hh = __float2bfloat16(val);
    size_t idx = (size_t)row*64 + j;
    oh[idx] = hh;
    ol[idx] = __float2bfloat16(val - __bfloat162float(hh));
}

// ---------------- launch -----------------------------------------------------------
extern "C" void kernel_launch(void* const* d_in, const int* in_sizes, int n_in,
                              void* d_out, int out_size)
{
    const float* x       = (const float*)d_in[0];
    const float* conv_qw = (const float*)d_in[1];
    const float* conv_qb = (const float*)d_in[2];
    const float* conv_kw = (const float*)d_in[3];
    const float* conv_kb = (const float*)d_in[4];
    const float* conv_vw = (const float*)d_in[5];
    const float* conv_vb = (const float*)d_in[6];
    const float* Wq      = (const float*)d_in[7];
    const float* bq      = (const float*)d_in[8];
    const float* Wk      = (const float*)d_in[9];
    const float* bk      = (const float*)d_in[10];
    const float* Wv      = (const float*)d_in[11];
    const float* bv      = (const float*)d_in[12];
    const float* W_ad    = (const float*)d_in[13];
    const float* b_ad    = (const float*)d_in[14];
    const float* W_au    = (const float*)d_in[15];
    const float* b_au    = (const float*)d_in[16];
    const float* W_beta  = (const float*)d_in[17];
    const float* b_beta  = (const float*)d_in[18];
    const float* rms_w   = (const float*)d_in[19];
    const float* W_gd    = (const float*)d_in[20];
    const float* b_gd    = (const float*)d_in[21];
    const float* W_gu    = (const float*)d_in[22];
    const float* b_gu    = (const float*)d_in[23];
    const float* Wo      = (const float*)d_in[24];
    const float* bo      = (const float*)d_in[25];

    float* out = (float*)d_out;
    float* y = out;
    const size_t y_elems = (size_t)MTOK * DD;
    const size_t s_elems = (size_t)BH * DKV * DKV;
    float* Sout = out + ((size_t)out_size >= y_elems + s_elems
                         ? (size_t)out_size - s_elems : y_elems);

    float *Qp, *Kp, *Vp, *Al, *Op, *hA, *hG, *Bt, *Gt;
    cudaGetSymbolAddress((void**)&Qp, g_Q);
    cudaGetSymbolAddress((void**)&Kp, g_K);
    cudaGetSymbolAddress((void**)&Vp, g_V);
    cudaGetSymbolAddress((void**)&Al, g_alpha);
    cudaGetSymbolAddress((void**)&Op, g_O);
    cudaGetSymbolAddress((void**)&hA, g_hidA);
    cudaGetSymbolAddress((void**)&hG, g_hidG);
    cudaGetSymbolAddress((void**)&Bt, g_beta);
    cudaGetSymbolAddress((void**)&Gt, g_gate);

    __nv_bfloat16 *qxh,*qxl,*kxh,*kxl,*vxh,*vxl,*oh,*ol;
    __nv_bfloat16 *wqh,*wql,*wkh,*wkl,*wvh,*wvl,*woh,*wol;
    cudaGetSymbolAddress((void**)&qxh, g_qxh); cudaGetSymbolAddress((void**)&qxl, g_qxl);
    cudaGetSymbolAddress((void**)&kxh, g_kxh); cudaGetSymbolAddress((void**)&kxl, g_kxl);
    cudaGetSymbolAddress((void**)&vxh, g_vxh); cudaGetSymbolAddress((void**)&vxl, g_vxl);
    cudaGetSymbolAddress((void**)&oh,  g_oh);  cudaGetSymbolAddress((void**)&ol,  g_ol);
    cudaGetSymbolAddress((void**)&wqh, g_wqh); cudaGetSymbolAddress((void**)&wql, g_wql);
    cudaGetSymbolAddress((void**)&wkh, g_wkh); cudaGetSymbolAddress((void**)&wkl, g_wkl);
    cudaGetSymbolAddress((void**)&wvh, g_wvh); cudaGetSymbolAddress((void**)&wvl, g_wvl);
    cudaGetSymbolAddress((void**)&woh, g_woh); cudaGetSymbolAddress((void**)&wol, g_wol);

    cudaFuncSetAttribute(hgemm<0>, cudaFuncAttributeMaxDynamicSharedMemorySize, HG_SMEM);
    cudaFuncSetAttribute(hgemm<1>, cudaFuncAttributeMaxDynamicSharedMemorySize, HG_SMEM);

    // 0) weight transpose + bf16 split (one launch)
    dim3 wgrid(DD/32, DD/32, 4), wblk(32, 32);
    wsplit_all<<<wgrid, wblk>>>(Wq, wqh, wql, Wk, wkh, wkl, Wv, wvh, wvl, Wo, woh, wol);

    // 1) causal depthwise convs + SiLU -> bf16 hi/lo
    conv_silu_split<<<(MTOK*DD + 255)/256, 256>>>(x, conv_qw, conv_qb,
                                                  conv_kw, conv_kb, conv_vw, conv_vb);

    // 2) fused x-projections: hA | hG | beta in one pass over x
    prep144<<<MTOK/64, 256>>>(x, W_ad, b_ad, W_gd, b_gd, W_beta, b_beta, hA, hG, Bt);

    // 3) Q/K/V projections on tensor cores (Q,K with fused bias+L2norm)
    dim3 tgrid(DD/128, MTOK/128);
    hgemm<1><<<tgrid, 256, HG_SMEM>>>(qxh, qxl, wqh, wql, bq, Qp, DD);
    hgemm<1><<<tgrid, 256, HG_SMEM>>>(kxh, kxl, wkh, wkl, bk, Kp, DD);
    hgemm<0><<<tgrid, 256, HG_SMEM>>>(vxh, vxl, wvh, wvl, bv, Vp, DD);

    // 4) alpha = sigmoid(hA @ W_au + b_au); gate = sigmoid(hG @ W_gu + b_gu)
    gemm128<2><<<dim3(DD/128, MTOK/128), 256>>>(hA, W_au, b_au, Al, MTOK, DD, RR);
    gateup<<<MTOK*HH/256, 256>>>(hG, W_gu, b_gu, Gt);

    // 5) barrier-free delta-rule scan (emits O and S_final)
    scan_kernel3<<<2*BH, 256>>>(Qp, Kp, Vp, Al, Bt, Op, Sout);

    // 6) RMSNorm + gate -> bf16 hi/lo
    normgate_split<<<(MTOK*HH)/4, 256>>>(Op, rms_w, Gt, oh, ol);

    // 7) y = O @ Wo + bo  (tensor cores)
    hgemm<0><<<tgrid, 256, HG_SMEM>>>(oh, ol, woh, wol, bo, y, DD);
}

// round 6
// speedup vs baseline: 2.4619x; 1.3808x over previous
#include <cuda_runtime.h>
#include <cuda_fp16.h>
#include <math.h>
#include <stdint.h>

// ---------------- problem constants ----------------
#define BB 4
#define TT 2048
#define DD 1024
#define HH 16
#define DKV 64
#define RR 64
#define KSZ 4
#define BH (BB*HH)      // 64
#define MTOK (BB*TT)    // 8192
#define EPSF 1e-6f

// ---------------- scratch (no cudaMalloc allowed) ----------------
__device__ __half g_qx[MTOK*DD];
__device__ __half g_kx[MTOK*DD];
__device__ __half g_vx[MTOK*DD];
__device__ __half g_og[MTOK*DD];
__device__ __half g_wq[DD*DD];
__device__ __half g_wk[DD*DD];
__device__ __half g_wv[DD*DD];
__device__ __half g_wo[DD*DD];
__device__ float g_Q [MTOK*DD];
__device__ float g_K [MTOK*DD];
__device__ float g_V [MTOK*DD];
__device__ float g_alpha[MTOK*DD];
__device__ float g_O [MTOK*DD];
__device__ float g_hidA[MTOK*RR];
__device__ float g_hidG[MTOK*RR];
__device__ float g_beta[MTOK*HH];
__device__ float g_gate[MTOK*HH];

__device__ __forceinline__ float sigmoidf_(float v){ return 1.0f/(1.0f+expf(-v)); }
__device__ __forceinline__ float siluf_(float v){ return v/(1.0f+expf(-v)); }

// ---------------- PTX helpers (baseline ISA only; NO sm_100a features) -------------
__device__ __forceinline__ uint32_t smem_u32(const void* p){
    uint32_t a;
    asm("{ .reg .u64 t; cvta.to.shared.u64 t, %1; cvt.u32.u64 %0, t; }" : "=r"(a) : "l"(p));
    return a;
}
#define CP_COMMIT() asm volatile("cp.async.commit_group;" ::: "memory")
#define CP_WAIT1()  asm volatile("cp.async.wait_group 1;" ::: "memory")
__device__ __forceinline__ void cp16(uint32_t dst, const void* src){
    asm volatile("cp.async.cg.shared.global [%0], [%1], 16;" :: "r"(dst), "l"(src) : "memory");
}
__device__ __forceinline__ void ldm4(uint32_t* r, uint32_t addr){
    asm volatile("ldmatrix.sync.aligned.m8n8.x4.shared.b16 {%0,%1,%2,%3}, [%4];"
        : "=r"(r[0]), "=r"(r[1]), "=r"(r[2]), "=r"(r[3]) : "r"(addr));
}
__device__ __forceinline__ void mma16816(float* d, const uint32_t* a, const uint32_t* b){
    asm volatile("mma.sync.aligned.m16n8k16.row.col.f32.f16.f16.f32 "
        "{%0,%1,%2,%3}, {%4,%5,%6,%7}, {%8,%9}, {%0,%1,%2,%3};"
        : "+f"(d[0]), "+f"(d[1]), "+f"(d[2]), "+f"(d[3])
        : "r"(a[0]), "r"(a[1]), "r"(a[2]), "r"(a[3]), "r"(b[0]), "r"(b[1]));
}

// ---------------- conv + SiLU -> fp16 ----------------
__global__ void conv_silu_f16(const float* __restrict__ x,
                              const float* __restrict__ wq, const float* __restrict__ bq,
                              const float* __restrict__ wk, const float* __restrict__ bk,
                              const float* __restrict__ wv, const float* __restrict__ bv)
{
    int idx = blockIdx.x*blockDim.x + threadIdx.x;
    if (idx >= MTOK*DD) return;
    int d = idx % DD;
    int t = (idx / DD) % TT;
    int b = idx / (DD*TT);

    float xs[KSZ];
#pragma unroll
    for (int j = 0; j < KSZ; j++) {
        int tt = t - (KSZ-1) + j;
        xs[j] = (tt >= 0) ? x[((size_t)b*TT + tt)*DD + d] : 0.0f;
    }
    float aq = bq[d], ak = bk[d], av = bv[d];
#pragma unroll
    for (int j = 0; j < KSZ; j++) {
        aq = fmaf(xs[j], wq[d*KSZ + j], aq);
        ak = fmaf(xs[j], wk[d*KSZ + j], ak);
        av = fmaf(xs[j], wv[d*KSZ + j], av);
    }
    g_qx[idx] = __float2half_rn(siluf_(aq));
    g_kx[idx] = __float2half_rn(siluf_(ak));
    g_vx[idx] = __float2half_rn(siluf_(av));
}

// ---------------- 4 weights: [K,N] f32 -> [N,K] fp16 (one launch) ------------------
__global__ void wsplit_all(const float* __restrict__ W0, __half* __restrict__ H0,
                           const float* __restrict__ W1, __half* __restrict__ H1,
                           const float* __restrict__ W2, __half* __restrict__ H2,
                           const float* __restrict__ W3, __half* __restrict__ H3)
{
    const float* W; __half* Th;
    switch (blockIdx.z) {
        case 0: W = W0; Th = H0; break;
        case 1: W = W1; Th = H1; break;
        case 2: W = W2; Th = H2; break;
        default: W = W3; Th = H3; break;
    }
    __shared__ float tile[32][33];
    int k = blockIdx.y*32 + threadIdx.y;
    int n = blockIdx.x*32 + threadIdx.x;
    tile[threadIdx.y][threadIdx.x] = W[(size_t)k*DD + n];
    __syncthreads();
    int n2 = blockIdx.x*32 + threadIdx.y;
    int k2 = blockIdx.y*32 + threadIdx.x;
    Th[(size_t)n2*DD + k2] = __float2half_rn(tile[threadIdx.x][threadIdx.y]);
}

// ---------------- HMMA fp16 single-pass GEMM, optional fused bias+L2norm -----------
// C[M,N] = A[M,1024] @ B[N,1024]^T + bias. BM=BN=128, BK=32, 8 warps (2m x 4n),
// 3-stage cp.async pipeline (3 CTAs/SM). Smem rows 80B -> ldmatrix conflict-free.
#define STAGES 3
#define AROWB 80
#define STAGE_A_BYTES (128*AROWB)
#define STAGE_BYTES   (2*STAGE_A_BYTES)
#define HG_SMEM       (STAGES*STAGE_BYTES)   // 61440
#define HG_NIT 32

template<int DO_L2>
__global__ __launch_bounds__(256)
void hgemm(const __half* __restrict__ Ap, const __half* __restrict__ Bp,
           const float* __restrict__ bias, float* __restrict__ C, int N_)
{
    extern __shared__ char smem[];
    uint32_t sb = smem_u32(smem);
    const int tid = threadIdx.x;
    const int wid = tid >> 5, lane = tid & 31;
    const int warp_m = wid >> 2, warp_n = wid & 3;
    const int m0 = blockIdx.y << 7, n0 = blockIdx.x << 7;

    float acc[4][4][4];
#pragma unroll
    for (int i = 0; i < 4; i++)
#pragma unroll
        for (int j = 0; j < 4; j++)
#pragma unroll
            for (int k = 0; k < 4; k++) acc[i][j][k] = 0.0f;

    const int lrow = tid >> 1;
    const int lcb  = (tid & 1) * 2;

    auto load_stage = [&](int it) {
        int kk = it << 5;
        uint32_t st = sb + (uint32_t)(it % STAGES) * STAGE_BYTES;
        const __half* ga = Ap + (size_t)(m0 + lrow)*DD + kk + lcb*8;
        uint32_t da = st + lrow*AROWB + lcb*16;
        cp16(da,      ga);
        cp16(da + 16, ga + 8);
        const __half* gb = Bp + (size_t)(n0 + lrow)*DD + kk + lcb*8;
        uint32_t db = st + STAGE_A_BYTES + lrow*AROWB + lcb*16;
        cp16(db,      gb);
        cp16(db + 16, gb + 8);
        CP_COMMIT();
    };

    load_stage(0); load_stage(1);

    const uint32_t a_row = warp_m*64 + (lane & 15);
    const uint32_t a_col = (lane >> 4) * 16;
    const uint32_t b_row = warp_n*32 + (lane & 7) + ((lane >> 4) & 1) * 8;
    const uint32_t b_col = ((lane >> 3) & 1) * 16;

    for (int i = 0; i < HG_NIT; i++) {
        CP_WAIT1();
        __syncthreads();
        int j = i + 2;
        if (j < HG_NIT) load_stage(j); else CP_COMMIT();

        uint32_t st = sb + (uint32_t)(i % STAGES) * STAGE_BYTES;
#pragma unroll
        for (int ks = 0; ks < 2; ks++) {
            uint32_t afr[4][4], bfr[2][4];
            uint32_t abase = st + a_row*AROWB + ks*32 + a_col;
#pragma unroll
            for (int mf = 0; mf < 4; mf++) ldm4(afr[mf], abase + mf*(16*AROWB));
            uint32_t bbase = st + STAGE_A_BYTES + b_row*AROWB + ks*32 + b_col;
#pragma unroll
            for (int np = 0; np < 2; np++) ldm4(bfr[np], bbase + np*(16*AROWB));
#pragma unroll
            for (int mf = 0; mf < 4; mf++)
#pragma unroll
                for (int nf = 0; nf < 4; nf++)
                    mma16816(acc[mf][nf], afr[mf], &bfr[nf >> 1][(nf & 1) * 2]);
        }
    }

    const int trow = lane >> 2, tcol = (lane & 3) * 2;

#pragma unroll
    for (int nf = 0; nf < 4; nf++) {
        int c = n0 + warp_n*32 + nf*8 + tcol;
        float b0 = bias[c], b1 = bias[c+1];
#pragma unroll
        for (int mf = 0; mf < 4; mf++) {
            acc[mf][nf][0] += b0; acc[mf][nf][1] += b1;
            acc[mf][nf][2] += b0; acc[mf][nf][3] += b1;
        }
    }

    if (DO_L2) {
        float rs[8];
#pragma unroll
        for (int mf = 0; mf < 4; mf++) {
            float s0 = 0.f, s1 = 0.f;
#pragma unroll
            for (int nf = 0; nf < 4; nf++) {
                s0 = fmaf(acc[mf][nf][0], acc[mf][nf][0], s0);
                s0 = fmaf(acc[mf][nf][1], acc[mf][nf][1], s0);
                s1 = fmaf(acc[mf][nf][2], acc[mf][nf][2], s1);
                s1 = fmaf(acc[mf][nf][3], acc[mf][nf][3], s1);
            }
            rs[mf*2]   = s0;
            rs[mf*2+1] = s1;
        }
#pragma unroll
        for (int r = 0; r < 8; r++) {
            rs[r] += __shfl_xor_sync(0xFFFFFFFFu, rs[r], 1);
            rs[r] += __shfl_xor_sync(0xFFFFFFFFu, rs[r], 2);
        }
        __syncthreads();
        float* sred = reinterpret_cast<float*>(smem);   // [4][128]
        if ((lane & 3) == 0) {
#pragma unroll
            for (int mf = 0; mf < 4; mf++) {
                int r = warp_m*64 + mf*16 + trow;
                sred[warp_n*128 + r]     = rs[mf*2];
                sred[warp_n*128 + r + 8] = rs[mf*2+1];
            }
        }
        __syncthreads();
        const int gp = (warp_n >> 1) * 2;
#pragma unroll
        for (int mf = 0; mf < 4; mf++) {
#pragma unroll
            for (int half = 0; half < 2; half++) {
                int r = warp_m*64 + mf*16 + trow + half*8;
                float tot = sred[gp*128 + r] + sred[(gp+1)*128 + r];
                float rn = rsqrtf(fmaxf(tot, EPSF));
                acc[mf][0][half*2]   *= rn; acc[mf][0][half*2+1] *= rn;
                acc[mf][1][half*2]   *= rn; acc[mf][1][half*2+1] *= rn;
                acc[mf][2][half*2]   *= rn; acc[mf][2][half*2+1] *= rn;
                acc[mf][3][half*2]   *= rn; acc[mf][3][half*2+1] *= rn;
            }
        }
    }

#pragma unroll
    for (int mf = 0; mf < 4; mf++) {
        int r = m0 + warp_m*64 + mf*16 + trow;
#pragma unroll
        for (int nf = 0; nf < 4; nf++) {
            int c = n0 + warp_n*32 + nf*8 + tcol;
            float* p0 = C + (size_t)r*N_ + c;
            float* p1 = C + (size_t)(r+8)*N_ + c;
            p0[0] = acc[mf][nf][0]; p0[1] = acc[mf][nf][1];
            p1[0] = acc[mf][nf][2]; p1[1] = acc[mf][nf][3];
        }
    }
}

// ---------------- fp32 SGEMM 128x128 (alpha-up, K=64, sigmoid) ---------------------
template<int ACT>
__global__ __launch_bounds__(256)
void gemm128(const float* __restrict__ A, const float* __restrict__ W,
             const float* __restrict__ bias, float* __restrict__ C,
             int M, int N, int K)
{
    __shared__ float As[8][128];
    __shared__ float Bs[8][128];

    const int tid = threadIdx.x;
    const int m0 = blockIdx.y * 128;
    const int n0 = blockIdx.x * 128;
    const int ty = tid >> 4;
    const int tx = tid & 15;
    const int arow = tid >> 1;
    const int ak   = (tid & 1) * 4;
    const int brow = tid >> 5;
    const int bcol = (tid & 31) * 4;

    float acc[8][8];
#pragma unroll
    for (int i = 0; i < 8; i++)
#pragma unroll
        for (int j = 0; j < 8; j++) acc[i][j] = 0.0f;

    for (int k0 = 0; k0 < K; k0 += 8) {
        float4 a4 = *reinterpret_cast<const float4*>(&A[(size_t)(m0 + arow)*K + k0 + ak]);
        float4 b4 = *reinterpret_cast<const float4*>(&W[(size_t)(k0 + brow)*N + n0 + bcol]);
        __syncthreads();
        As[ak+0][arow] = a4.x; As[ak+1][arow] = a4.y;
        As[ak+2][arow] = a4.z; As[ak+3][arow] = a4.w;
        *reinterpret_cast<float4*>(&Bs[brow][bcol]) = b4;
        __syncthreads();
#pragma unroll
        for (int k = 0; k < 8; k++) {
            float ra[8], rb[8];
#pragma unroll
            for (int i = 0; i < 8; i++) ra[i] = As[k][ty*8 + i];
#pragma unroll
            for (int i = 0; i < 8; i++) rb[i] = Bs[k][tx*8 + i];
#pragma unroll
            for (int i = 0; i < 8; i++)
#pragma unroll
                for (int j = 0; j < 8; j++)
                    acc[i][j] = fmaf(ra[i], rb[j], acc[i][j]);
        }
    }

#pragma unroll
    for (int i = 0; i < 8; i++) {
        int m = m0 + ty*8 + i;
#pragma unroll
        for (int j = 0; j < 8; j++) {
            int n = n0 + tx*8 + j;
            float c = acc[i][j] + bias[n];
            if (ACT == 1) c = siluf_(c);
            else if (ACT == 2) c = sigmoidf_(c);
            C[(size_t)m*N + n] = c;
        }
    }
}

// ---------------- fused x-projections: hA (silu) | hG (silu) | beta (sigmoid) ------
__global__ __launch_bounds__(256)
void prep144(const float* __restrict__ x,
             const float* __restrict__ W_ad, const float* __restrict__ b_ad,
             const float* __restrict__ W_gd, const float* __restrict__ b_gd,
             const float* __restrict__ W_bt, const float* __restrict__ b_bt,
             float* __restrict__ hA, float* __restrict__ hG, float* __restrict__ Bt)
{
    __shared__ float Xs[16][68];
    __shared__ float Ws[16][144];

    const int tid = threadIdx.x;
    const int m0 = blockIdx.x * 64;
    const int ty = tid >> 4, tx = tid & 15;

    float acc[4][9];
#pragma unroll
    for (int i = 0; i < 4; i++)
#pragma unroll
        for (int j = 0; j < 9; j++) acc[i][j] = 0.0f;

    const int xrow = tid >> 2, xk = (tid & 3) * 4;
    const int wk = tid >> 4, wc = tid & 15;

    for (int k0 = 0; k0 < DD; k0 += 16) {
        __syncthreads();
        float4 xv = *reinterpret_cast<const float4*>(&x[(size_t)(m0 + xrow)*DD + k0 + xk]);
        Xs[xk+0][xrow] = xv.x; Xs[xk+1][xrow] = xv.y;
        Xs[xk+2][xrow] = xv.z; Xs[xk+3][xrow] = xv.w;
#pragma unroll
        for (int j = 0; j < 9; j++) {
            int c = wc + j*16;
            float w;
            if (c < 64)       w = W_ad[(size_t)(k0 + wk)*64 + c];
            else if (c < 128) w = W_gd[(size_t)(k0 + wk)*64 + (c - 64)];
            else              w = W_bt[(size_t)(k0 + wk)*16 + (c - 128)];
            Ws[wk][c] = w;
        }
        __syncthreads();
#pragma unroll
        for (int k = 0; k < 16; k++) {
            float ra[4], rb[9];
#pragma unroll
            for (int i = 0; i < 4; i++) ra[i] = Xs[k][ty*4 + i];
#pragma unroll
            for (int j = 0; j < 9; j++) rb[j] = Ws[k][tx + j*16];
#pragma unroll
            for (int i = 0; i < 4; i++)
#pragma unroll
                for (int j = 0; j < 9; j++)
                    acc[i][j] = fmaf(ra[i], rb[j], acc[i][j]);
        }
    }

#pragma unroll
    for (int i = 0; i < 4; i++) {
        int m = m0 + ty*4 + i;
#pragma unroll
        for (int j = 0; j < 9; j++) {
            int c = tx + j*16;
            float v = acc[i][j];
            if (c < 64)       hA[(size_t)m*64 + c]        = siluf_(v + b_ad[c]);
            else if (c < 128) hG[(size_t)m*64 + (c-64)]   = siluf_(v + b_gd[c-64]);
            else              Bt[(size_t)m*16 + (c-128)]  = sigmoidf_(v + b_bt[c-128]);
        }
    }
}

// ---------------- gate-up: gate = sigmoid(hidG @ W_gu + b_gu) ----------------------
__global__ __launch_bounds__(256)
void gateup(const float* __restrict__ hG, const float* __restrict__ W_gu,
            const float* __restrict__ b_gu, float* __restrict__ Gt)
{
    int gidx = blockIdx.x*256 + threadIdx.x;
    int m = gidx >> 4, h = gidx & 15;
    const float* row = hG + (size_t)m*64;
    float s = b_gu[h];
#pragma unroll 8
    for (int i = 0; i < 64; i++) s = fmaf(row[i], W_gu[i*16 + h], s);
    Gt[gidx] = sigmoidf_(s);
}

// ---------------- gated delta-rule scan, barrier-free -------------------------------
__global__ __launch_bounds__(256)
void scan_kernel3(const float* __restrict__ Q, const float* __restrict__ K,
                  const float* __restrict__ V, const float* __restrict__ A,
                  const float* __restrict__ Beta,
                  float* __restrict__ O, float* __restrict__ Sout)
{
    const int blk = blockIdx.x;
    const int bh  = blk >> 1, hf = blk & 1;
    const int b = bh / HH, h = bh % HH;
    const int tid = threadIdx.x;
    const int e   = tid & 7;
    const int col = hf*32 + (tid >> 3);
    const int r0  = e * 8;

    const size_t base = ((size_t)b*TT)*DD + (size_t)h*64;
    const size_t bbase = (size_t)b*TT*HH + h;

    float S[8];
#pragma unroll
    for (int i = 0; i < 8; i++) S[i] = 0.0f;

    float4 kb[4][2], ab[4][2], qb[4][2];
    float  vb[4], bb[4];

#define SCAN_LOAD(t_, s_) do { \
    const float4* kp = reinterpret_cast<const float4*>(K + base + (size_t)(t_)*DD + r0); \
    const float4* ap = reinterpret_cast<const float4*>(A + base + (size_t)(t_)*DD + r0); \
    const float4* qp = reinterpret_cast<const float4*>(Q + base + (size_t)(t_)*DD + r0); \
    kb[s_][0] = kp[0]; kb[s_][1] = kp[1]; \
    ab[s_][0] = ap[0]; ab[s_][1] = ap[1]; \
    qb[s_][0] = qp[0]; qb[s_][1] = qp[1]; \
    vb[s_] = V[base + (size_t)(t_)*DD + col]; \
    bb[s_] = Beta[bbase + (size_t)(t_)*HH]; \
} while(0)

    SCAN_LOAD(0, 0); SCAN_LOAD(1, 1); SCAN_LOAD(2, 2);

#pragma unroll 4
    for (int t = 0; t < TT; t++) {
        const int s = t & 3;
        if (t + 3 < TT) SCAN_LOAD(t + 3, (t + 3) & 3);

        float k_[8], a_[8], q_[8];
        *reinterpret_cast<float4*>(&k_[0]) = kb[s][0];
        *reinterpret_cast<float4*>(&k_[4]) = kb[s][1];
        *reinterpret_cast<float4*>(&a_[0]) = ab[s][0];
        *reinterpret_cast<float4*>(&a_[4]) = ab[s][1];
        *reinterpret_cast<float4*>(&q_[0]) = qb[s][0];
        *reinterpret_cast<float4*>(&q_[4]) = qb[s][1];

        float p0 = 0.f, p1 = 0.f;
#pragma unroll
        for (int i = 0; i < 8; i += 2) {
            S[i]   *= a_[i];   p0 = fmaf(k_[i],   S[i],   p0);
            S[i+1] *= a_[i+1]; p1 = fmaf(k_[i+1], S[i+1], p1);
        }
        float p = p0 + p1;
        p += __shfl_xor_sync(0xFFFFFFFFu, p, 1);
        p += __shfl_xor_sync(0xFFFFFFFFu, p, 2);
        p += __shfl_xor_sync(0xFFFFFFFFu, p, 4);

        float c = bb[s] * (vb[s] - p);

        float o0 = 0.f, o1 = 0.f;
#pragma unroll
        for (int i = 0; i < 8; i += 2) {
            S[i]   = fmaf(k_[i],   c, S[i]);   o0 = fmaf(S[i],   q_[i],   o0);
            S[i+1] = fmaf(k_[i+1], c, S[i+1]); o1 = fmaf(S[i+1], q_[i+1], o1);
        }
        float o = o0 + o1;
        o += __shfl_xor_sync(0xFFFFFFFFu, o, 1);
        o += __shfl_xor_sync(0xFFFFFFFFu, o, 2);
        o += __shfl_xor_sync(0xFFFFFFFFu, o, 4);

        if (e == 0)
            O[base + (size_t)t*DD + col] = o;
    }
#undef SCAN_LOAD

#pragma unroll
    for (int i = 0; i < 8; i++)
        Sout[(size_t)bh*DKV*DKV + (size_t)(r0 + i)*DKV + col] = S[i];
}

// ---------------- headwise RMSNorm + gate -> fp16 ----------------------------------
__global__ __launch_bounds__(256)
void normgate_f16(const float* __restrict__ O, const float* __restrict__ rms_w,
                  const float* __restrict__ gate, __half* __restrict__ og)
{
    int row = blockIdx.x*4 + (threadIdx.x >> 6);
    int j   = threadIdx.x & 63;
    int h   = row % HH;

    float v = O[(size_t)row*64 + j];
    float ss = v*v;
#pragma unroll
    for (int o = 16; o; o >>= 1) ss += __shfl_xor_sync(0xFFFFFFFFu, ss, o);

    __shared__ float part[8];
    if ((threadIdx.x & 31) == 0) part[threadIdx.x >> 5] = ss;
    __syncthreads();
    int w0 = (threadIdx.x >> 6) * 2;
    float tot = part[w0] + part[w0 + 1];

    float rn  = rsqrtf(tot * (1.0f/64.0f) + EPSF);
    og[(size_t)row*64 + j] = __float2half_rn(v * rn * rms_w[h*64 + j] * gate[row]);
}

// ---------------- launch -----------------------------------------------------------
extern "C" void kernel_launch(void* const* d_in, const int* in_sizes, int n_in,
                              void* d_out, int out_size)
{
    const float* x       = (const float*)d_in[0];
    const float* conv_qw = (const float*)d_in[1];
    const float* conv_qb = (const float*)d_in[2];
    const float* conv_kw = (const float*)d_in[3];
    const float* conv_kb = (const float*)d_in[4];
    const float* conv_vw = (const float*)d_in[5];
    const float* conv_vb = (const float*)d_in[6];
    const float* Wq      = (const float*)d_in[7];
    const float* bq      = (const float*)d_in[8];
    const float* Wk      = (const float*)d_in[9];
    const float* bk      = (const float*)d_in[10];
    const float* Wv      = (const float*)d_in[11];
    const float* bv      = (const float*)d_in[12];
    const float* W_ad    = (const float*)d_in[13];
    const float* b_ad    = (const float*)d_in[14];
    const float* W_au    = (const float*)d_in[15];
    const float* b_au    = (const float*)d_in[16];
    const float* W_beta  = (const float*)d_in[17];
    const float* b_beta  = (const float*)d_in[18];
    const float* rms_w   = (const float*)d_in[19];
    const float* W_gd    = (const float*)d_in[20];
    const float* b_gd    = (const float*)d_in[21];
    const float* W_gu    = (const float*)d_in[22];
    const float* b_gu    = (const float*)d_in[23];
    const float* Wo      = (const float*)d_in[24];
    const float* bo      = (const float*)d_in[25];

    float* out = (float*)d_out;
    float* y = out;
    const size_t y_elems = (size_t)MTOK * DD;
    const size_t s_elems = (size_t)BH * DKV * DKV;
    float* Sout = out + ((size_t)out_size >= y_elems + s_elems
                         ? (size_t)out_size - s_elems : y_elems);

    float *Qp, *Kp, *Vp, *Al, *Op, *hA, *hG, *Bt, *Gt;
    cudaGetSymbolAddress((void**)&Qp, g_Q);
    cudaGetSymbolAddress((void**)&Kp, g_K);
    cudaGetSymbolAddress((void**)&Vp, g_V);
    cudaGetSymbolAddress((void**)&Al, g_alpha);
    cudaGetSymbolAddress((void**)&Op, g_O);
    cudaGetSymbolAddress((void**)&hA, g_hidA);
    cudaGetSymbolAddress((void**)&hG, g_hidG);
    cudaGetSymbolAddress((void**)&Bt, g_beta);
    cudaGetSymbolAddress((void**)&Gt, g_gate);

    __half *qx,*kx,*vx,*og,*wq,*wk,*wv,*wo;
    cudaGetSymbolAddress((void**)&qx, g_qx);
    cudaGetSymbolAddress((void**)&kx, g_kx);
    cudaGetSymbolAddress((void**)&vx, g_vx);
    cudaGetSymbolAddress((void**)&og, g_og);
    cudaGetSymbolAddress((void**)&wq, g_wq);
    cudaGetSymbolAddress((void**)&wk, g_wk);
    cudaGetSymbolAddress((void**)&wv, g_wv);
    cudaGetSymbolAddress((void**)&wo, g_wo);

    cudaFuncSetAttribute(hgemm<0>, cudaFuncAttributeMaxDynamicSharedMemorySize, HG_SMEM);
    cudaFuncSetAttribute(hgemm<1>, cudaFuncAttributeMaxDynamicSharedMemorySize, HG_SMEM);

    // 0) weight transpose -> fp16 [N,K] (one launch)
    dim3 wgrid(DD/32, DD/32, 4), wblk(32, 32);
    wsplit_all<<<wgrid, wblk>>>(Wq, wq, Wk, wk, Wv, wv, Wo, wo);

    // 1) causal depthwise convs + SiLU -> fp16
    conv_silu_f16<<<(MTOK*DD + 255)/256, 256>>>(x, conv_qw, conv_qb,
                                                conv_kw, conv_kb, conv_vw, conv_vb);

    // 2) fused x-projections: hA | hG | beta in one pass over x
    prep144<<<MTOK/64, 256>>>(x, W_ad, b_ad, W_gd, b_gd, W_beta, b_beta, hA, hG, Bt);

    // 3) Q/K/V projections, fp16 tensor cores (Q,K with fused bias+L2norm)
    dim3 tgrid(DD/128, MTOK/128);
    hgemm<1><<<tgrid, 256, HG_SMEM>>>(qx, wq, bq, Qp, DD);
    hgemm<1><<<tgrid, 256, HG_SMEM>>>(kx, wk, bk, Kp, DD);
    hgemm<0><<<tgrid, 256, HG_SMEM>>>(vx, wv, bv, Vp, DD);

    // 4) alpha = sigmoid(hA @ W_au + b_au); gate = sigmoid(hG @ W_gu + b_gu)
    gemm128<2><<<dim3(DD/128, MTOK/128), 256>>>(hA, W_au, b_au, Al, MTOK, DD, RR);
    gateup<<<MTOK*HH/256, 256>>>(hG, W_gu, b_gu, Gt);

    // 5) barrier-free delta-rule scan (emits O and S_final)
    scan_kernel3<<<2*BH, 256>>>(Qp, Kp, Vp, Al, Bt, Op, Sout);

    // 6) RMSNorm + gate -> fp16
    normgate_f16<<<(MTOK*HH)/4, 256>>>(Op, rms_w, Gt, og);

    // 7) y = O @ Wo + bo  (fp16 tensor cores)
    hgemm<0><<<tgrid, 256, HG_SMEM>>>(og, wo, bo, y, DD);
}

// round 7
// speedup vs baseline: 2.7648x; 1.1230x over previous
#include <cuda_runtime.h>
#include <cuda_fp16.h>
#include <math.h>
#include <stdint.h>

// ---------------- problem constants ----------------
#define BB 4
#define TT 2048
#define DD 1024
#define HH 16
#define DKV 64
#define RR 64
#define KSZ 4
#define BH (BB*HH)      // 64
#define MTOK (BB*TT)    // 8192
#define EPSF 1e-6f

// ---------------- scratch (no cudaMalloc allowed) ----------------
__device__ __half g_qx[MTOK*DD];
__device__ __half g_kx[MTOK*DD];
__device__ __half g_vx[MTOK*DD];
__device__ __half g_og[MTOK*DD];
__device__ __half g_wq[DD*DD];
__device__ __half g_wk[DD*DD];
__device__ __half g_wv[DD*DD];
__device__ __half g_wo[DD*DD];
__device__ float g_Q [MTOK*DD];
__device__ float g_K [MTOK*DD];
__device__ float g_V [MTOK*DD];
__device__ float g_alpha[MTOK*DD];
__device__ float g_O [MTOK*DD];
__device__ float g_hidA[MTOK*RR];
__device__ float g_hidG[MTOK*RR];
__device__ float g_beta[MTOK*HH];
__device__ float g_gate[MTOK*HH];

__device__ __forceinline__ float sigmoidf_(float v){ return 1.0f/(1.0f+expf(-v)); }
__device__ __forceinline__ float siluf_(float v){ return v/(1.0f+expf(-v)); }

// ---------------- PTX helpers (baseline ISA only; NO sm_100a features) -------------
__device__ __forceinline__ uint32_t smem_u32(const void* p){
    uint32_t a;
    asm("{ .reg .u64 t; cvta.to.shared.u64 t, %1; cvt.u32.u64 %0, t; }" : "=r"(a) : "l"(p));
    return a;
}
#define CP_COMMIT() asm volatile("cp.async.commit_group;" ::: "memory")
#define CP_WAIT1()  asm volatile("cp.async.wait_group 1;" ::: "memory")
__device__ __forceinline__ void cp16(uint32_t dst, const void* src){
    asm volatile("cp.async.cg.shared.global [%0], [%1], 16;" :: "r"(dst), "l"(src) : "memory");
}
__device__ __forceinline__ void ldm4(uint32_t* r, uint32_t addr){
    asm volatile("ldmatrix.sync.aligned.m8n8.x4.shared.b16 {%0,%1,%2,%3}, [%4];"
        : "=r"(r[0]), "=r"(r[1]), "=r"(r[2]), "=r"(r[3]) : "r"(addr));
}
__device__ __forceinline__ void mma16816(float* d, const uint32_t* a, const uint32_t* b){
    asm volatile("mma.sync.aligned.m16n8k16.row.col.f32.f16.f16.f32 "
        "{%0,%1,%2,%3}, {%4,%5,%6,%7}, {%8,%9}, {%0,%1,%2,%3};"
        : "+f"(d[0]), "+f"(d[1]), "+f"(d[2]), "+f"(d[3])
        : "r"(a[0]), "r"(a[1]), "r"(a[2]), "r"(a[3]), "r"(b[0]), "r"(b[1]));
}

// ---------------- conv + SiLU -> fp16 ----------------
__global__ void conv_silu_f16(const float* __restrict__ x,
                              const float* __restrict__ wq, const float* __restrict__ bq,
                              const float* __restrict__ wk, const float* __restrict__ bk,
                              const float* __restrict__ wv, const float* __restrict__ bv)
{
    int idx = blockIdx.x*blockDim.x + threadIdx.x;
    if (idx >= MTOK*DD) return;
    int d = idx % DD;
    int t = (idx / DD) % TT;
    int b = idx / (DD*TT);

    float xs[KSZ];
#pragma unroll
    for (int j = 0; j < KSZ; j++) {
        int tt = t - (KSZ-1) + j;
        xs[j] = (tt >= 0) ? x[((size_t)b*TT + tt)*DD + d] : 0.0f;
    }
    float aq = bq[d], ak = bk[d], av = bv[d];
#pragma unroll
    for (int j = 0; j < KSZ; j++) {
        aq = fmaf(xs[j], wq[d*KSZ + j], aq);
        ak = fmaf(xs[j], wk[d*KSZ + j], ak);
        av = fmaf(xs[j], wv[d*KSZ + j], av);
    }
    g_qx[idx] = __float2half_rn(siluf_(aq));
    g_kx[idx] = __float2half_rn(siluf_(ak));
    g_vx[idx] = __float2half_rn(siluf_(av));
}

// ---------------- 4 weights: [K,N] f32 -> [N,K] fp16 (one launch) ------------------
__global__ void wsplit_all(const float* __restrict__ W0, __half* __restrict__ H0,
                           const float* __restrict__ W1, __half* __restrict__ H1,
                           const float* __restrict__ W2, __half* __restrict__ H2,
                           const float* __restrict__ W3, __half* __restrict__ H3)
{
    const float* W; __half* Th;
    switch (blockIdx.z) {
        case 0: W = W0; Th = H0; break;
        case 1: W = W1; Th = H1; break;
        case 2: W = W2; Th = H2; break;
        default: W = W3; Th = H3; break;
    }
    __shared__ float tile[32][33];
    int k = blockIdx.y*32 + threadIdx.y;
    int n = blockIdx.x*32 + threadIdx.x;
    tile[threadIdx.y][threadIdx.x] = W[(size_t)k*DD + n];
    __syncthreads();
    int n2 = blockIdx.x*32 + threadIdx.y;
    int k2 = blockIdx.y*32 + threadIdx.x;
    Th[(size_t)n2*DD + k2] = __float2half_rn(tile[threadIdx.x][threadIdx.y]);
}

// ---------------- HMMA fp16 single-pass GEMM, optional fused bias+L2norm -----------
#define STAGES 3
#define AROWB 80
#define STAGE_A_BYTES (128*AROWB)
#define STAGE_BYTES   (2*STAGE_A_BYTES)
#define HG_SMEM       (STAGES*STAGE_BYTES)   // 61440
#define HG_NIT 32

template<int DO_L2>
__global__ __launch_bounds__(256)
void hgemm(const __half* __restrict__ Ap, const __half* __restrict__ Bp,
           const float* __restrict__ bias, float* __restrict__ C, int N_)
{
    extern __shared__ char smem[];
    uint32_t sb = smem_u32(smem);
    const int tid = threadIdx.x;
    const int wid = tid >> 5, lane = tid & 31;
    const int warp_m = wid >> 2, warp_n = wid & 3;
    const int m0 = blockIdx.y << 7, n0 = blockIdx.x << 7;

    float acc[4][4][4];
#pragma unroll
    for (int i = 0; i < 4; i++)
#pragma unroll
        for (int j = 0; j < 4; j++)
#pragma unroll
            for (int k = 0; k < 4; k++) acc[i][j][k] = 0.0f;

    const int lrow = tid >> 1;
    const int lcb  = (tid & 1) * 2;

    auto load_stage = [&](int it) {
        int kk = it << 5;
        uint32_t st = sb + (uint32_t)(it % STAGES) * STAGE_BYTES;
        const __half* ga = Ap + (size_t)(m0 + lrow)*DD + kk + lcb*8;
        uint32_t da = st + lrow*AROWB + lcb*16;
        cp16(da,      ga);
        cp16(da + 16, ga + 8);
        const __half* gb = Bp + (size_t)(n0 + lrow)*DD + kk + lcb*8;
        uint32_t db = st + STAGE_A_BYTES + lrow*AROWB + lcb*16;
        cp16(db,      gb);
        cp16(db + 16, gb + 8);
        CP_COMMIT();
    };

    load_stage(0); load_stage(1);

    const uint32_t a_row = warp_m*64 + (lane & 15);
    const uint32_t a_col = (lane >> 4) * 16;
    const uint32_t b_row = warp_n*32 + (lane & 7) + ((lane >> 4) & 1) * 8;
    const uint32_t b_col = ((lane >> 3) & 1) * 16;

    for (int i = 0; i < HG_NIT; i++) {
        CP_WAIT1();
        __syncthreads();
        int j = i + 2;
        if (j < HG_NIT) load_stage(j); else CP_COMMIT();

        uint32_t st = sb + (uint32_t)(i % STAGES) * STAGE_BYTES;
#pragma unroll
        for (int ks = 0; ks < 2; ks++) {
            uint32_t afr[4][4], bfr[2][4];
            uint32_t abase = st + a_row*AROWB + ks*32 + a_col;
#pragma unroll
            for (int mf = 0; mf < 4; mf++) ldm4(afr[mf], abase + mf*(16*AROWB));
            uint32_t bbase = st + STAGE_A_BYTES + b_row*AROWB + ks*32 + b_col;
#pragma unroll
            for (int np = 0; np < 2; np++) ldm4(bfr[np], bbase + np*(16*AROWB));
#pragma unroll
            for (int mf = 0; mf < 4; mf++)
#pragma unroll
                for (int nf = 0; nf < 4; nf++)
                    mma16816(acc[mf][nf], afr[mf], &bfr[nf >> 1][(nf & 1) * 2]);
        }
    }

    const int trow = lane >> 2, tcol = (lane & 3) * 2;

#pragma unroll
    for (int nf = 0; nf < 4; nf++) {
        int c = n0 + warp_n*32 + nf*8 + tcol;
        float b0 = bias[c], b1 = bias[c+1];
#pragma unroll
        for (int mf = 0; mf < 4; mf++) {
            acc[mf][nf][0] += b0; acc[mf][nf][1] += b1;
            acc[mf][nf][2] += b0; acc[mf][nf][3] += b1;
        }
    }

    if (DO_L2) {
        float rs[8];
#pragma unroll
        for (int mf = 0; mf < 4; mf++) {
            float s0 = 0.f, s1 = 0.f;
#pragma unroll
            for (int nf = 0; nf < 4; nf++) {
                s0 = fmaf(acc[mf][nf][0], acc[mf][nf][0], s0);
                s0 = fmaf(acc[mf][nf][1], acc[mf][nf][1], s0);
                s1 = fmaf(acc[mf][nf][2], acc[mf][nf][2], s1);
                s1 = fmaf(acc[mf][nf][3], acc[mf][nf][3], s1);
            }
            rs[mf*2]   = s0;
            rs[mf*2+1] = s1;
        }
#pragma unroll
        for (int r = 0; r < 8; r++) {
            rs[r] += __shfl_xor_sync(0xFFFFFFFFu, rs[r], 1);
            rs[r] += __shfl_xor_sync(0xFFFFFFFFu, rs[r], 2);
        }
        __syncthreads();
        float* sred = reinterpret_cast<float*>(smem);   // [4][128]
        if ((lane & 3) == 0) {
#pragma unroll
            for (int mf = 0; mf < 4; mf++) {
                int r = warp_m*64 + mf*16 + trow;
                sred[warp_n*128 + r]     = rs[mf*2];
                sred[warp_n*128 + r + 8] = rs[mf*2+1];
            }
        }
        __syncthreads();
        const int gp = (warp_n >> 1) * 2;
#pragma unroll
        for (int mf = 0; mf < 4; mf++) {
#pragma unroll
            for (int half = 0; half < 2; half++) {
                int r = warp_m*64 + mf*16 + trow + half*8;
                float tot = sred[gp*128 + r] + sred[(gp+1)*128 + r];
                float rn = rsqrtf(fmaxf(tot, EPSF));
                acc[mf][0][half*2]   *= rn; acc[mf][0][half*2+1] *= rn;
                acc[mf][1][half*2]   *= rn; acc[mf][1][half*2+1] *= rn;
                acc[mf][2][half*2]   *= rn; acc[mf][2][half*2+1] *= rn;
                acc[mf][3][half*2]   *= rn; acc[mf][3][half*2+1] *= rn;
            }
        }
    }

#pragma unroll
    for (int mf = 0; mf < 4; mf++) {
        int r = m0 + warp_m*64 + mf*16 + trow;
#pragma unroll
        for (int nf = 0; nf < 4; nf++) {
            int c = n0 + warp_n*32 + nf*8 + tcol;
            float* p0 = C + (size_t)r*N_ + c;
            float* p1 = C + (size_t)(r+8)*N_ + c;
            p0[0] = acc[mf][nf][0]; p0[1] = acc[mf][nf][1];
            p1[0] = acc[mf][nf][2]; p1[1] = acc[mf][nf][3];
        }
    }
}

// ---------------- fp32 SGEMM 128x128 (alpha-up, K=64, sigmoid) ---------------------
template<int ACT>
__global__ __launch_bounds__(256)
void gemm128(const float* __restrict__ A, const float* __restrict__ W,
             const float* __restrict__ bias, float* __restrict__ C,
             int M, int N, int K)
{
    __shared__ float As[8][128];
    __shared__ float Bs[8][128];

    const int tid = threadIdx.x;
    const int m0 = blockIdx.y * 128;
    const int n0 = blockIdx.x * 128;
    const int ty = tid >> 4;
    const int tx = tid & 15;
    const int arow = tid >> 1;
    const int ak   = (tid & 1) * 4;
    const int brow = tid >> 5;
    const int bcol = (tid & 31) * 4;

    float acc[8][8];
#pragma unroll
    for (int i = 0; i < 8; i++)
#pragma unroll
        for (int j = 0; j < 8; j++) acc[i][j] = 0.0f;

    for (int k0 = 0; k0 < K; k0 += 8) {
        float4 a4 = *reinterpret_cast<const float4*>(&A[(size_t)(m0 + arow)*K + k0 + ak]);
        float4 b4 = *reinterpret_cast<const float4*>(&W[(size_t)(k0 + brow)*N + n0 + bcol]);
        __syncthreads();
        As[ak+0][arow] = a4.x; As[ak+1][arow] = a4.y;
        As[ak+2][arow] = a4.z; As[ak+3][arow] = a4.w;
        *reinterpret_cast<float4*>(&Bs[brow][bcol]) = b4;
        __syncthreads();
#pragma unroll
        for (int k = 0; k < 8; k++) {
            float ra[8], rb[8];
#pragma unroll
            for (int i = 0; i < 8; i++) ra[i] = As[k][ty*8 + i];
#pragma unroll
            for (int i = 0; i < 8; i++) rb[i] = Bs[k][tx*8 + i];
#pragma unroll
            for (int i = 0; i < 8; i++)
#pragma unroll
                for (int j = 0; j < 8; j++)
                    acc[i][j] = fmaf(ra[i], rb[j], acc[i][j]);
        }
    }

#pragma unroll
    for (int i = 0; i < 8; i++) {
        int m = m0 + ty*8 + i;
#pragma unroll
        for (int j = 0; j < 8; j++) {
            int n = n0 + tx*8 + j;
            float c = acc[i][j] + bias[n];
            if (ACT == 1) c = siluf_(c);
            else if (ACT == 2) c = sigmoidf_(c);
            C[(size_t)m*N + n] = c;
        }
    }
}

// ---------------- fused x-projections: hA (silu) | hG (silu) | beta (sigmoid) ------
__global__ __launch_bounds__(256)
void prep144(const float* __restrict__ x,
             const float* __restrict__ W_ad, const float* __restrict__ b_ad,
             const float* __restrict__ W_gd, const float* __restrict__ b_gd,
             const float* __restrict__ W_bt, const float* __restrict__ b_bt,
             float* __restrict__ hA, float* __restrict__ hG, float* __restrict__ Bt)
{
    __shared__ float Xs[16][68];
    __shared__ float Ws[16][144];

    const int tid = threadIdx.x;
    const int m0 = blockIdx.x * 64;
    const int ty = tid >> 4, tx = tid & 15;

    float acc[4][9];
#pragma unroll
    for (int i = 0; i < 4; i++)
#pragma unroll
        for (int j = 0; j < 9; j++) acc[i][j] = 0.0f;

    const int xrow = tid >> 2, xk = (tid & 3) * 4;
    const int wk = tid >> 4, wc = tid & 15;

    for (int k0 = 0; k0 < DD; k0 += 16) {
        __syncthreads();
        float4 xv = *reinterpret_cast<const float4*>(&x[(size_t)(m0 + xrow)*DD + k0 + xk]);
        Xs[xk+0][xrow] = xv.x; Xs[xk+1][xrow] = xv.y;
        Xs[xk+2][xrow] = xv.z; Xs[xk+3][xrow] = xv.w;
#pragma unroll
        for (int j = 0; j < 9; j++) {
            int c = wc + j*16;
            float w;
            if (c < 64)       w = W_ad[(size_t)(k0 + wk)*64 + c];
            else if (c < 128) w = W_gd[(size_t)(k0 + wk)*64 + (c - 64)];
            else              w = W_bt[(size_t)(k0 + wk)*16 + (c - 128)];
            Ws[wk][c] = w;
        }
        __syncthreads();
#pragma unroll
        for (int k = 0; k < 16; k++) {
            float ra[4], rb[9];
#pragma unroll
            for (int i = 0; i < 4; i++) ra[i] = Xs[k][ty*4 + i];
#pragma unroll
            for (int j = 0; j < 9; j++) rb[j] = Ws[k][tx + j*16];
#pragma unroll
            for (int i = 0; i < 4; i++)
#pragma unroll
                for (int j = 0; j < 9; j++)
                    acc[i][j] = fmaf(ra[i], rb[j], acc[i][j]);
        }
    }

#pragma unroll
    for (int i = 0; i < 4; i++) {
        int m = m0 + ty*4 + i;
#pragma unroll
        for (int j = 0; j < 9; j++) {
            int c = tx + j*16;
            float v = acc[i][j];
            if (c < 64)       hA[(size_t)m*64 + c]        = siluf_(v + b_ad[c]);
            else if (c < 128) hG[(size_t)m*64 + (c-64)]   = siluf_(v + b_gd[c-64]);
            else              Bt[(size_t)m*16 + (c-128)]  = sigmoidf_(v + b_bt[c-128]);
        }
    }
}

// ---------------- gate-up: gate = sigmoid(hidG @ W_gu + b_gu) ----------------------
__global__ __launch_bounds__(256)
void gateup(const float* __restrict__ hG, const float* __restrict__ W_gu,
            const float* __restrict__ b_gu, float* __restrict__ Gt)
{
    int gidx = blockIdx.x*256 + threadIdx.x;
    int m = gidx >> 4, h = gidx & 15;
    const float* row = hG + (size_t)m*64;
    float s = b_gu[h];
#pragma unroll 8
    for (int i = 0; i < 64; i++) s = fmaf(row[i], W_gu[i*16 + h], s);
    Gt[gidx] = sigmoidf_(s);
}

// ---------------- gated delta-rule scan v5: barrier-free + deferred o-reduction ----
// 128 blocks = (head, col-half). lane bits[2:0] = row-eighth, bits[7:3] = local col.
// p-reduction (recurrence path) per step via 3 shfl; o-reduction batched every 4
// steps (12 pipelined shfls ~90cyc per 4 steps instead of 4x78 on the path).
__global__ __launch_bounds__(256)
void scan_kernel5(const float* __restrict__ Q, const float* __restrict__ K,
                  const float* __restrict__ V, const float* __restrict__ A,
                  const float* __restrict__ Beta,
                  float* __restrict__ O, float* __restrict__ Sout)
{
    const int blk = blockIdx.x;
    const int bh  = blk >> 1, hf = blk & 1;
    const int b = bh / HH, h = bh % HH;
    const int tid = threadIdx.x;
    const int e   = tid & 7;
    const int col = hf*32 + (tid >> 3);
    const int r0  = e * 8;

    const size_t base = ((size_t)b*TT)*DD + (size_t)h*64;
    const size_t bbase = (size_t)b*TT*HH + h;

    float S[8];
#pragma unroll
    for (int i = 0; i < 8; i++) S[i] = 0.0f;

    float4 kb[4][2], ab[4][2], qb[4][2];
    float  vb[4], bb[4], ob[4];

#define SCAN_LOAD(t_, s_) do { \
    const float4* kp = reinterpret_cast<const float4*>(K + base + (size_t)(t_)*DD + r0); \
    const float4* ap = reinterpret_cast<const float4*>(A + base + (size_t)(t_)*DD + r0); \
    const float4* qp = reinterpret_cast<const float4*>(Q + base + (size_t)(t_)*DD + r0); \
    kb[s_][0] = kp[0]; kb[s_][1] = kp[1]; \
    ab[s_][0] = ap[0]; ab[s_][1] = ap[1]; \
    qb[s_][0] = qp[0]; qb[s_][1] = qp[1]; \
    vb[s_] = V[base + (size_t)(t_)*DD + col]; \
    bb[s_] = Beta[bbase + (size_t)(t_)*HH]; \
} while(0)

    SCAN_LOAD(0, 0); SCAN_LOAD(1, 1); SCAN_LOAD(2, 2);

    for (int t0 = 0; t0 < TT; t0 += 4) {
#pragma unroll
        for (int u = 0; u < 4; u++) {
            const int t = t0 + u;
            const int s = t & 3;
            if (t + 3 < TT) SCAN_LOAD(t + 3, (t + 3) & 3);

            float k_[8], a_[8], q_[8];
            *reinterpret_cast<float4*>(&k_[0]) = kb[s][0];
            *reinterpret_cast<float4*>(&k_[4]) = kb[s][1];
            *reinterpret_cast<float4*>(&a_[0]) = ab[s][0];
            *reinterpret_cast<float4*>(&a_[4]) = ab[s][1];
            *reinterpret_cast<float4*>(&q_[0]) = qb[s][0];
            *reinterpret_cast<float4*>(&q_[4]) = qb[s][1];

            // recurrence-critical: decay + k^T S -> shfl-reduce -> rank-1 update
            float p0 = 0.f, p1 = 0.f;
#pragma unroll
            for (int i = 0; i < 8; i += 2) {
                S[i]   *= a_[i];   p0 = fmaf(k_[i],   S[i],   p0);
                S[i+1] *= a_[i+1]; p1 = fmaf(k_[i+1], S[i+1], p1);
            }
            float p = p0 + p1;
            p += __shfl_xor_sync(0xFFFFFFFFu, p, 1);
            p += __shfl_xor_sync(0xFFFFFFFFu, p, 2);
            p += __shfl_xor_sync(0xFFFFFFFFu, p, 4);

            float c = bb[s] * (vb[s] - p);

            float o0 = 0.f, o1 = 0.f;
#pragma unroll
            for (int i = 0; i < 8; i += 2) {
                S[i]   = fmaf(k_[i],   c, S[i]);   o0 = fmaf(S[i],   q_[i],   o0);
                S[i+1] = fmaf(k_[i+1], c, S[i+1]); o1 = fmaf(S[i+1], q_[i+1], o1);
            }
            ob[u] = o0 + o1;     // deferred: reduced after the 4-step group
        }

        // batched o-reduction: 4 independent values x 3 rounds, pipelined
#pragma unroll
        for (int r = 1; r <= 4; r <<= 1) {
            float t0v = __shfl_xor_sync(0xFFFFFFFFu, ob[0], r);
            float t1v = __shfl_xor_sync(0xFFFFFFFFu, ob[1], r);
            float t2v = __shfl_xor_sync(0xFFFFFFFFu, ob[2], r);
            float t3v = __shfl_xor_sync(0xFFFFFFFFu, ob[3], r);
            ob[0] += t0v; ob[1] += t1v; ob[2] += t2v; ob[3] += t3v;
        }
        if (e == 0) {
#pragma unroll
            for (int u = 0; u < 4; u++)
                O[base + (size_t)(t0 + u)*DD + col] = ob[u];
        }
    }
#undef SCAN_LOAD

#pragma unroll
    for (int i = 0; i < 8; i++)
        Sout[(size_t)bh*DKV*DKV + (size_t)(r0 + i)*DKV + col] = S[i];
}

// ---------------- headwise RMSNorm + gate -> fp16 ----------------------------------
__global__ __launch_bounds__(256)
void normgate_f16(const float* __restrict__ O, const float* __restrict__ rms_w,
                  const float* __restrict__ gate, __half* __restrict__ og)
{
    int row = blockIdx.x*4 + (threadIdx.x >> 6);
    int j   = threadIdx.x & 63;
    int h   = row % HH;

    float v = O[(size_t)row*64 + j];
    float ss = v*v;
#pragma unroll
    for (int o = 16; o; o >>= 1) ss += __shfl_xor_sync(0xFFFFFFFFu, ss, o);

    __shared__ float part[8];
    if ((threadIdx.x & 31) == 0) part[threadIdx.x >> 5] = ss;
    __syncthreads();
    int w0 = (threadIdx.x >> 6) * 2;
    float tot = part[w0] + part[w0 + 1];

    float rn  = rsqrtf(tot * (1.0f/64.0f) + EPSF);
    og[(size_t)row*64 + j] = __float2half_rn(v * rn * rms_w[h*64 + j] * gate[row]);
}

// ---------------- launch (multi-stream fork/join, graph-capturable) ----------------
extern "C" void kernel_launch(void* const* d_in, const int* in_sizes, int n_in,
                              void* d_out, int out_size)
{
    const float* x       = (const float*)d_in[0];
    const float* conv_qw = (const float*)d_in[1];
    const float* conv_qb = (const float*)d_in[2];
    const float* conv_kw = (const float*)d_in[3];
    const float* conv_kb = (const float*)d_in[4];
    const float* conv_vw = (const float*)d_in[5];
    const float* conv_vb = (const float*)d_in[6];
    const float* Wq      = (const float*)d_in[7];
    const float* bq      = (const float*)d_in[8];
    const float* Wk      = (const float*)d_in[9];
    const float* bk      = (const float*)d_in[10];
    const float* Wv      = (const float*)d_in[11];
    const float* bv      = (const float*)d_in[12];
    const float* W_ad    = (const float*)d_in[13];
    const float* b_ad    = (const float*)d_in[14];
    const float* W_au    = (const float*)d_in[15];
    const float* b_au    = (const float*)d_in[16];
    const float* W_beta  = (const float*)d_in[17];
    const float* b_beta  = (const float*)d_in[18];
    const float* rms_w   = (const float*)d_in[19];
    const float* W_gd    = (const float*)d_in[20];
    const float* b_gd    = (const float*)d_in[21];
    const float* W_gu    = (const float*)d_in[22];
    const float* b_gu    = (const float*)d_in[23];
    const float* Wo      = (const float*)d_in[24];
    const float* bo      = (const float*)d_in[25];

    float* out = (float*)d_out;
    float* y = out;
    const size_t y_elems = (size_t)MTOK * DD;
    const size_t s_elems = (size_t)BH * DKV * DKV;
    float* Sout = out + ((size_t)out_size >= y_elems + s_elems
                         ? (size_t)out_size - s_elems : y_elems);

    float *Qp, *Kp, *Vp, *Al, *Op, *hA, *hG, *Bt, *Gt;
    cudaGetSymbolAddress((void**)&Qp, g_Q);
    cudaGetSymbolAddress((void**)&Kp, g_K);
    cudaGetSymbolAddress((void**)&Vp, g_V);
    cudaGetSymbolAddress((void**)&Al, g_alpha);
    cudaGetSymbolAddress((void**)&Op, g_O);
    cudaGetSymbolAddress((void**)&hA, g_hidA);
    cudaGetSymbolAddress((void**)&hG, g_hidG);
    cudaGetSymbolAddress((void**)&Bt, g_beta);
    cudaGetSymbolAddress((void**)&Gt, g_gate);

    __half *qx,*kx,*vx,*og,*wq,*wk,*wv,*wo;
    cudaGetSymbolAddress((void**)&qx, g_qx);
    cudaGetSymbolAddress((void**)&kx, g_kx);
    cudaGetSymbolAddress((void**)&vx, g_vx);
    cudaGetSymbolAddress((void**)&og, g_og);
    cudaGetSymbolAddress((void**)&wq, g_wq);
    cudaGetSymbolAddress((void**)&wk, g_wk);
    cudaGetSymbolAddress((void**)&wv, g_wv);
    cudaGetSymbolAddress((void**)&wo, g_wo);

    cudaFuncSetAttribute(hgemm<0>, cudaFuncAttributeMaxDynamicSharedMemorySize, HG_SMEM);
    cudaFuncSetAttribute(hgemm<1>, cudaFuncAttributeMaxDynamicSharedMemorySize, HG_SMEM);

    // side streams/events: created once (host objects only; no device allocation)
    static cudaStream_t s1 = nullptr, s2 = nullptr;
    static cudaEvent_t evRoot = nullptr, evW = nullptr, evAlpha = nullptr, evGate = nullptr;
    if (!s1) {
        cudaStreamCreateWithFlags(&s1, cudaStreamNonBlocking);
        cudaStreamCreateWithFlags(&s2, cudaStreamNonBlocking);
        cudaEventCreateWithFlags(&evRoot,  cudaEventDisableTiming);
        cudaEventCreateWithFlags(&evW,     cudaEventDisableTiming);
        cudaEventCreateWithFlags(&evAlpha, cudaEventDisableTiming);
        cudaEventCreateWithFlags(&evGate,  cudaEventDisableTiming);
    }

    // fork
    cudaEventRecord(evRoot, 0);
    cudaStreamWaitEvent(s1, evRoot, 0);
    cudaStreamWaitEvent(s2, evRoot, 0);

    // s1: weight transpose -> fp16
    dim3 wgrid(DD/32, DD/32, 4), wblk(32, 32);
    wsplit_all<<<wgrid, wblk, 0, s1>>>(Wq, wq, Wk, wk, Wv, wv, Wo, wo);
    cudaEventRecord(evW, s1);

    // s2: x-projections -> alpha, gate
    prep144<<<MTOK/64, 256, 0, s2>>>(x, W_ad, b_ad, W_gd, b_gd, W_beta, b_beta, hA, hG, Bt);
    gemm128<2><<<dim3(DD/128, MTOK/128), 256, 0, s2>>>(hA, W_au, b_au, Al, MTOK, DD, RR);
    cudaEventRecord(evAlpha, s2);
    gateup<<<MTOK*HH/256, 256, 0, s2>>>(hG, W_gu, b_gu, Gt);
    cudaEventRecord(evGate, s2);

    // main stream: convs, then Q/K/V GEMMs (need weights)
    conv_silu_f16<<<(MTOK*DD + 255)/256, 256>>>(x, conv_qw, conv_qb,
                                                conv_kw, conv_kb, conv_vw, conv_vb);
    cudaStreamWaitEvent(0, evW, 0);
    dim3 tgrid(DD/128, MTOK/128);
    hgemm<1><<<tgrid, 256, HG_SMEM>>>(qx, wq, bq, Qp, DD);
    hgemm<1><<<tgrid, 256, HG_SMEM>>>(kx, wk, bk, Kp, DD);
    hgemm<0><<<tgrid, 256, HG_SMEM>>>(vx, wv, bv, Vp, DD);

    // join alpha/beta, run scan
    cudaStreamWaitEvent(0, evAlpha, 0);
    scan_kernel5<<<2*BH, 256>>>(Qp, Kp, Vp, Al, Bt, Op, Sout);

    // join gate, normalize, output GEMM
    cudaStreamWaitEvent(0, evGate, 0);
    normgate_f16<<<(MTOK*HH)/4, 256>>>(Op, rms_w, Gt, og);
    hgemm<0><<<tgrid, 256, HG_SMEM>>>(og, wo, bo, y, DD);
}